// round 1
// baseline (speedup 1.0000x reference)
#include <cuda_runtime.h>
#include <math.h>

#define DIMC 256
#define HEADS 8
#define HD 32
#define WSZ 8
#define SSZ 4
#define NTOK 64
#define BATCH 16
#define IMG 64
#define ROWS (BATCH*IMG*IMG)   /* 65536 token rows */
#define QSCALE 0.17677669529663687f

// ---------------- scratch (device globals; no allocation allowed) ----------------
__device__ __align__(16) float g_xw  [ROWS*DIMC];      // LN1 + shift + window partition
__device__ __align__(16) float g_qkv [ROWS*3*DIMC];    // qkv projections
__device__ __align__(16) float g_attn[ROWS*DIMC];      // attention output (window layout)
__device__ __align__(16) float g_y   [ROWS*DIMC];      // x + proj (natural layout)
__device__ __align__(16) float g_yn  [ROWS*DIMC];      // LN2(y)
__device__ __align__(16) float g_m1  [ROWS*4*DIMC];    // gelu(fc1)

// ---------------- LayerNorm (optionally fused shift+window-partition gather) ----
__global__ void ln_kernel(const float* __restrict__ in, const float* __restrict__ g,
                          const float* __restrict__ b, float* __restrict__ out,
                          int shiftmode)
{
    int o = blockIdx.x;          // output row
    int c = threadIdx.x;         // 0..255
    int src = o;
    if (shiftmode) {
        int widx = o >> 6, n = o & 63;
        int bb = widx >> 6, wi = widx & 63;
        int wy = wi >> 3, wx = wi & 7;
        int iy = n >> 3,  ix = n & 7;
        int sh = (wy*8 + iy + SSZ) & 63;
        int sw = (wx*8 + ix + SSZ) & 63;
        src = bb*4096 + sh*64 + sw;
    }
    float v = in[(size_t)src*DIMC + c];
    __shared__ float red[16];
    float s = v, s2 = v*v;
    #pragma unroll
    for (int off = 16; off; off >>= 1) {
        s  += __shfl_xor_sync(0xffffffffu, s,  off);
        s2 += __shfl_xor_sync(0xffffffffu, s2, off);
    }
    int warp = c >> 5, lane = c & 31;
    if (lane == 0) { red[warp] = s; red[warp+8] = s2; }
    __syncthreads();
    if (warp == 0) {
        float a  = (lane < 8) ? red[lane]   : 0.f;
        float a2 = (lane < 8) ? red[lane+8] : 0.f;
        #pragma unroll
        for (int off = 4; off; off >>= 1) {
            a  += __shfl_xor_sync(0xffffffffu, a,  off);
            a2 += __shfl_xor_sync(0xffffffffu, a2, off);
        }
        if (lane == 0) { red[0] = a; red[1] = a2; }
    }
    __syncthreads();
    float mean = red[0] * (1.f/DIMC);
    float var  = red[1] * (1.f/DIMC) - mean*mean;
    float r = rsqrtf(var + 1e-5f);
    out[(size_t)o*DIMC + c] = (v - mean) * r * g[c] + b[c];
}

// ---------------- generic 128x128x8 fp32 GEMM, 8x8 microtile -------------------
// MODE 0: C = A@B + bias
// MODE 1: C = gelu(A@B + bias)            (exact erf gelu)
// MODE 2: C[dst(r)] = res[dst(r)] + A@B + bias   (window-reverse + shift scatter)
// MODE 3: C = res + A@B + bias
template<int MODE>
__global__ void gemm_kernel(const float* __restrict__ A, const float* __restrict__ B,
                            const float* __restrict__ bias, const float* __restrict__ res,
                            float* __restrict__ C, int M, int N, int K)
{
    const int BM = 128, BN = 128, BK = 8;
    __shared__ float As[BK][BM];
    __shared__ float Bs[BK][BN];
    int bm = blockIdx.y * BM;
    int bn = blockIdx.x * BN;
    int tid = threadIdx.x;           // 0..255
    int tx = tid & 15, ty = tid >> 4;

    float acc[8][8];
    #pragma unroll
    for (int i = 0; i < 8; i++)
        #pragma unroll
        for (int j = 0; j < 8; j++) acc[i][j] = 0.f;

    int a_m = tid >> 1;
    int a_k = (tid & 1) * 4;
    int b_k = tid >> 5;
    int b_n = (tid & 31) * 4;

    float4 av = *reinterpret_cast<const float4*>(&A[(size_t)(bm + a_m)*K + a_k]);
    float4 bv = *reinterpret_cast<const float4*>(&B[(size_t)b_k*N + bn + b_n]);

    for (int k0 = 0; k0 < K; k0 += BK) {
        As[a_k+0][a_m] = av.x; As[a_k+1][a_m] = av.y;
        As[a_k+2][a_m] = av.z; As[a_k+3][a_m] = av.w;
        *reinterpret_cast<float4*>(&Bs[b_k][b_n]) = bv;
        __syncthreads();
        if (k0 + BK < K) {
            av = *reinterpret_cast<const float4*>(&A[(size_t)(bm + a_m)*K + (k0 + BK) + a_k]);
            bv = *reinterpret_cast<const float4*>(&B[(size_t)(k0 + BK + b_k)*N + bn + b_n]);
        }
        #pragma unroll
        for (int kk = 0; kk < BK; kk++) {
            float4 a0 = *reinterpret_cast<const float4*>(&As[kk][ty*8]);
            float4 a1 = *reinterpret_cast<const float4*>(&As[kk][ty*8+4]);
            float4 b0 = *reinterpret_cast<const float4*>(&Bs[kk][tx*8]);
            float4 b1 = *reinterpret_cast<const float4*>(&Bs[kk][tx*8+4]);
            float ar[8] = {a0.x,a0.y,a0.z,a0.w,a1.x,a1.y,a1.z,a1.w};
            float br[8] = {b0.x,b0.y,b0.z,b0.w,b1.x,b1.y,b1.z,b1.w};
            #pragma unroll
            for (int i = 0; i < 8; i++)
                #pragma unroll
                for (int j = 0; j < 8; j++)
                    acc[i][j] += ar[i]*br[j];
        }
        __syncthreads();
    }

    int row0 = bm + ty*8;
    int col0 = bn + tx*8;
    #pragma unroll
    for (int i = 0; i < 8; i++) {
        int r = row0 + i;
        size_t dst = r;
        if (MODE == 2) {
            int widx = r >> 6, n = r & 63;
            int bb = widx >> 6, wi = widx & 63;
            int wy = wi >> 3, wx = wi & 7;
            int iy = n >> 3,  ix = n & 7;
            int dh = (wy*8 + iy + SSZ) & 63;
            int dw = (wx*8 + ix + SSZ) & 63;
            dst = (size_t)(bb*4096 + dh*64 + dw);
        }
        #pragma unroll
        for (int j = 0; j < 8; j++) {
            int cidx = col0 + j;
            float v = acc[i][j] + bias[cidx];
            if (MODE == 1) {
                v = 0.5f * v * (1.f + erff(v * 0.7071067811865475f));
            } else if (MODE == 2 || MODE == 3) {
                v += res[dst*(size_t)N + cidx];
            }
            C[dst*(size_t)N + cidx] = v;
        }
    }
}

// ---------------- windowed attention: one block per (window, head) --------------
__global__ void attn_kernel(const float* __restrict__ qkv, const float* __restrict__ rpb,
                            float* __restrict__ out)
{
    int bid  = blockIdx.x;      // widx*8 + head
    int head = bid & 7;
    int widx = bid >> 3;
    int wi = widx & 63;
    int wy = wi >> 3, wx = wi & 7;

    __shared__ float qs[64][33];
    __shared__ float ks[64][33];
    __shared__ float vs[64][33];
    __shared__ float sc[64][65];
    __shared__ int   regid[64];

    int tid = threadIdx.x;      // 0..255
    for (int idx = tid; idx < 2048; idx += 256) {
        int n = idx >> 5, d = idx & 31;
        size_t base = (size_t)(widx*64 + n) * (3*DIMC) + head*32 + d;
        qs[n][d] = qkv[base]           * QSCALE;
        ks[n][d] = qkv[base + DIMC];
        vs[n][d] = qkv[base + 2*DIMC];
    }
    if (tid < 64) {
        int iy = tid >> 3, ix = tid & 7;
        int rh = (wy < 7) ? 0 : ((iy < SSZ) ? 1 : 2);
        int rw = (wx < 7) ? 0 : ((ix < SSZ) ? 1 : 2);
        regid[tid] = rh*3 + rw;
    }
    __syncthreads();

    // scores: thread (ty,tx) owns rows p0..p0+3 (blocked), cols tx+16j (strided)
    int ty = tid >> 4, tx = tid & 15;
    int p0 = ty * 4;
    float s[4][4];
    #pragma unroll
    for (int i = 0; i < 4; i++)
        #pragma unroll
        for (int j = 0; j < 4; j++) s[i][j] = 0.f;

    #pragma unroll 8
    for (int d = 0; d < 32; d++) {
        float a[4], b[4];
        #pragma unroll
        for (int i = 0; i < 4; i++) a[i] = qs[p0+i][d];
        #pragma unroll
        for (int j = 0; j < 4; j++) b[j] = ks[tx + 16*j][d];
        #pragma unroll
        for (int i = 0; i < 4; i++)
            #pragma unroll
            for (int j = 0; j < 4; j++) s[i][j] += a[i]*b[j];
    }
    #pragma unroll
    for (int i = 0; i < 4; i++) {
        int p = p0 + i;
        #pragma unroll
        for (int j = 0; j < 4; j++) {
            int q = tx + 16*j;
            int dx = (p & 7) - (q & 7);
            int dy = (p >> 3) - (q >> 3);
            int rpi = (dx + 7)*15 + (dy + 7);
            float v = s[i][j] + __ldg(&rpb[rpi*HEADS + head]);
            if (regid[p] == regid[q]) v -= 100.f;
            sc[p][q] = v;
        }
    }
    __syncthreads();

    // softmax per row (threads 0..63)
    if (tid < 64) {
        float mx = -1e30f;
        #pragma unroll 8
        for (int q = 0; q < 64; q++) mx = fmaxf(mx, sc[tid][q]);
        float sum = 0.f;
        #pragma unroll 8
        for (int q = 0; q < 64; q++) {
            float e = __expf(sc[tid][q] - mx);
            sc[tid][q] = e;
            sum += e;
        }
        float inv = 1.f / sum;
        #pragma unroll 8
        for (int q = 0; q < 64; q++) sc[tid][q] *= inv;
    }
    __syncthreads();

    // out = probs @ V : thread owns 4 rows x 2 cols
    int d0  = (tid & 15) * 2;
    int pp0 = (tid >> 4) * 4;
    float o[4][2];
    #pragma unroll
    for (int i = 0; i < 4; i++) { o[i][0] = 0.f; o[i][1] = 0.f; }
    #pragma unroll 8
    for (int kk = 0; kk < 64; kk++) {
        float b0 = vs[kk][d0], b1 = vs[kk][d0+1];
        #pragma unroll
        for (int i = 0; i < 4; i++) {
            float a = sc[pp0+i][kk];
            o[i][0] += a*b0;
            o[i][1] += a*b1;
        }
    }
    #pragma unroll
    for (int i = 0; i < 4; i++) {
        size_t row = (size_t)(widx*64 + pp0 + i);
        out[row*DIMC + head*32 + d0    ] = o[i][0];
        out[row*DIMC + head*32 + d0 + 1] = o[i][1];
    }
}

// ---------------------------------- launch --------------------------------------
extern "C" void kernel_launch(void* const* d_in, const int* in_sizes, int n_in,
                              void* d_out, int out_size)
{
    const float* x      = (const float*)d_in[0];
    const float* n1g    = (const float*)d_in[1];
    const float* n1b    = (const float*)d_in[2];
    const float* qkv_w  = (const float*)d_in[3];
    const float* qkv_b  = (const float*)d_in[4];
    const float* rpb    = (const float*)d_in[5];
    const float* proj_w = (const float*)d_in[6];
    const float* proj_b = (const float*)d_in[7];
    const float* n2g    = (const float*)d_in[8];
    const float* n2b    = (const float*)d_in[9];
    const float* fc1_w  = (const float*)d_in[10];
    const float* fc1_b  = (const float*)d_in[11];
    const float* fc2_w  = (const float*)d_in[12];
    const float* fc2_b  = (const float*)d_in[13];
    float* out = (float*)d_out;

    float *xw, *qkvbuf, *attn, *y, *yn, *m1;
    cudaGetSymbolAddress((void**)&xw,     g_xw);
    cudaGetSymbolAddress((void**)&qkvbuf, g_qkv);
    cudaGetSymbolAddress((void**)&attn,   g_attn);
    cudaGetSymbolAddress((void**)&y,      g_y);
    cudaGetSymbolAddress((void**)&yn,     g_yn);
    cudaGetSymbolAddress((void**)&m1,     g_m1);

    // 1) LN1 + cyclic shift + window partition
    ln_kernel<<<ROWS, 256>>>(x, n1g, n1b, xw, 1);
    // 2) QKV GEMM: [65536,256] @ [256,768]
    gemm_kernel<0><<<dim3(768/128, ROWS/128), 256>>>(xw, qkv_w, qkv_b, nullptr, qkvbuf,
                                                     ROWS, 768, 256);
    // 3) windowed attention
    attn_kernel<<<ROWS/64*HEADS, 256>>>(qkvbuf, rpb, attn);
    // 4) proj GEMM + window-reverse/shift scatter + residual(x) -> y
    gemm_kernel<2><<<dim3(256/128, ROWS/128), 256>>>(attn, proj_w, proj_b, x, y,
                                                     ROWS, 256, 256);
    // 5) LN2
    ln_kernel<<<ROWS, 256>>>(y, n2g, n2b, yn, 0);
    // 6) fc1 + exact GELU
    gemm_kernel<1><<<dim3(1024/128, ROWS/128), 256>>>(yn, fc1_w, fc1_b, nullptr, m1,
                                                      ROWS, 1024, 256);
    // 7) fc2 + residual with ORIGINAL shortcut x -> out
    gemm_kernel<3><<<dim3(256/128, ROWS/128), 256>>>(m1, fc2_w, fc2_b, x, out,
                                                     ROWS, 256, 1024);
}

// round 3
// speedup vs baseline: 2.5850x; 2.5850x over previous
#include <cuda_runtime.h>
#include <math.h>
#include <cstdint>

#define DIMC 256
#define HEADS 8
#define WSZ 8
#define SSZ 4
#define BATCH 16
#define IMG 64
#define ROWS (BATCH*IMG*IMG)   /* 65536 token rows */
#define QSCALE 0.17677669529663687f

// ---------------- scratch (device globals; no allocation allowed) ----------------
__device__ __align__(16) float g_xw  [ROWS*DIMC];      // LN1 + shift + window partition (tf32)
__device__ __align__(16) float g_qkv [ROWS*3*DIMC];    // qkv projections
__device__ __align__(16) float g_attn[ROWS*DIMC];      // attention output (window layout, tf32)
__device__ __align__(16) float g_y   [ROWS*DIMC];      // x + proj (natural layout)
__device__ __align__(16) float g_yn  [ROWS*DIMC];      // LN2(y) (tf32)
__device__ __align__(16) float g_m1  [ROWS*4*DIMC];    // gelu(fc1) (tf32)
// transposed weights  WT[n*K + k] = W[k*N + n]   (tf32-rounded)
__device__ __align__(16) float g_wt_qkv [768*256];
__device__ __align__(16) float g_wt_proj[256*256];
__device__ __align__(16) float g_wt_fc1 [1024*256];
__device__ __align__(16) float g_wt_fc2 [256*1024];

// ---------------- helpers --------------------------------------------------------
__device__ __forceinline__ float tf32r(float f) {
    uint32_t u;
    asm("cvt.rna.tf32.f32 %0, %1;" : "=r"(u) : "f"(f));
    return __uint_as_float(u);
}
__device__ __forceinline__ uint32_t smem_u32(const void* p) {
    uint32_t a;
    asm("{ .reg .u64 t; cvta.to.shared.u64 t, %1; cvt.u32.u64 %0, t; }" : "=r"(a) : "l"(p));
    return a;
}
#define CP_ASYNC16(dst, src) \
    asm volatile("cp.async.cg.shared.global [%0], [%1], 16;" :: "r"(dst), "l"(src))
#define CP_COMMIT() asm volatile("cp.async.commit_group;")
#define CP_WAIT1()  asm volatile("cp.async.wait_group 1;")
#define CP_WAIT0()  asm volatile("cp.async.wait_group 0;")

__device__ __forceinline__ void mma_tf32(float c[4], uint32_t a0, uint32_t a1,
                                         uint32_t a2, uint32_t a3,
                                         uint32_t b0, uint32_t b1) {
    asm volatile(
        "mma.sync.aligned.m16n8k8.row.col.f32.tf32.tf32.f32 "
        "{%0,%1,%2,%3}, {%4,%5,%6,%7}, {%8,%9}, {%0,%1,%2,%3};"
        : "+f"(c[0]), "+f"(c[1]), "+f"(c[2]), "+f"(c[3])
        : "r"(a0), "r"(a1), "r"(a2), "r"(a3), "r"(b0), "r"(b1));
}

// ---------------- LayerNorm (optionally fused shift+window-partition gather) ----
__global__ void ln_kernel(const float* __restrict__ in, const float* __restrict__ g,
                          const float* __restrict__ b, float* __restrict__ out,
                          int shiftmode)
{
    int o = blockIdx.x;          // output row
    int c = threadIdx.x;         // 0..255
    int src = o;
    if (shiftmode) {
        int widx = o >> 6, n = o & 63;
        int bb = widx >> 6, wi = widx & 63;
        int wy = wi >> 3, wx = wi & 7;
        int iy = n >> 3,  ix = n & 7;
        int sh = (wy*8 + iy + SSZ) & 63;
        int sw = (wx*8 + ix + SSZ) & 63;
        src = bb*4096 + sh*64 + sw;
    }
    float v = in[(size_t)src*DIMC + c];
    __shared__ float red[16];
    float s = v, s2 = v*v;
    #pragma unroll
    for (int off = 16; off; off >>= 1) {
        s  += __shfl_xor_sync(0xffffffffu, s,  off);
        s2 += __shfl_xor_sync(0xffffffffu, s2, off);
    }
    int warp = c >> 5, lane = c & 31;
    if (lane == 0) { red[warp] = s; red[warp+8] = s2; }
    __syncthreads();
    if (warp == 0) {
        float a  = (lane < 8) ? red[lane]   : 0.f;
        float a2 = (lane < 8) ? red[lane+8] : 0.f;
        #pragma unroll
        for (int off = 4; off; off >>= 1) {
            a  += __shfl_xor_sync(0xffffffffu, a,  off);
            a2 += __shfl_xor_sync(0xffffffffu, a2, off);
        }
        if (lane == 0) { red[0] = a; red[1] = a2; }
    }
    __syncthreads();
    float mean = red[0] * (1.f/DIMC);
    float var  = red[1] * (1.f/DIMC) - mean*mean;
    float r = rsqrtf(var + 1e-5f);
    out[(size_t)o*DIMC + c] = tf32r((v - mean) * r * g[c] + b[c]);
}

// ---------------- weight transpose (+ tf32 round): WT[n*K+k] = W[k*N+n] --------
__global__ void transpose_kernel(const float* __restrict__ w, float* __restrict__ wt,
                                 int K, int N)
{
    __shared__ float t[32][33];
    int k0 = blockIdx.y*32, n0 = blockIdx.x*32;
    int tx = threadIdx.x, ty = threadIdx.y;   // 32 x 8
    #pragma unroll
    for (int i = ty; i < 32; i += 8) t[i][tx] = w[(size_t)(k0+i)*N + n0 + tx];
    __syncthreads();
    #pragma unroll
    for (int i = ty; i < 32; i += 8) wt[(size_t)(n0+i)*K + k0 + tx] = tf32r(t[tx][i]);
}

// ============== tf32 mma.sync GEMM: 128x128x32 tiles, cp.async 2-stage ==========
// D[M,N] = A[M,K] @ B[K,N]  (B supplied transposed: BT[N,K]); both tf32-rounded.
// MODE 0: +bias    MODE 1: tf32(gelu(+bias))
// MODE 2: scatter(window-reverse+shift) + res + bias    MODE 3: res + bias
#define PAD 36                      /* floats per 32-float row in smem */
#define STG 4608                    /* 128*PAD floats per stage */
template<int MODE>
__global__ __launch_bounds__(256, 2)
void mma_gemm(const float* __restrict__ A, const float* __restrict__ BT,
              const float* __restrict__ bias, const float* __restrict__ res,
              float* __restrict__ C, int M, int N, int K)
{
    extern __shared__ float sm[];   // As0 | As1 | Bs0 | Bs1 : 4*STG floats
    int tid = threadIdx.x, wid = tid >> 5, lane = tid & 31;
    int g = lane >> 2, ct = lane & 3;
    int wm = wid & 1, wn = wid >> 1;          // 2 x 4 warp grid
    int bm = blockIdx.y * 128, bn = blockIdx.x * 128;
    const float* Ab = A  + (size_t)bm * K;
    const float* Bb = BT + (size_t)bn * K;
    const int T = K / 32;

    int f_row = tid >> 3, f_c4 = tid & 7;     // fill: 4 iters of (row, 16B-chunk)

    #define FILL(t, s) do { \
        float* as_ = sm + (s)*STG; \
        float* bs_ = sm + 2*STG + (s)*STG; \
        _Pragma("unroll") \
        for (int i = 0; i < 4; i++) { \
            int row = f_row + i*32; \
            uint32_t da = smem_u32(as_ + row*PAD + f_c4*4); \
            uint32_t db = smem_u32(bs_ + row*PAD + f_c4*4); \
            CP_ASYNC16(da, Ab + (size_t)row*K + (t)*32 + f_c4*4); \
            CP_ASYNC16(db, Bb + (size_t)row*K + (t)*32 + f_c4*4); \
        } \
        CP_COMMIT(); \
    } while (0)

    float acc[4][4][4];
    #pragma unroll
    for (int i = 0; i < 4; i++)
        #pragma unroll
        for (int j = 0; j < 4; j++)
            #pragma unroll
            for (int e = 0; e < 4; e++) acc[i][j][e] = 0.f;

    FILL(0, 0);
    FILL(1, 1);

    for (int t = 0; t < T; t++) {
        int s = t & 1;
        if (t + 1 < T) CP_WAIT1(); else CP_WAIT0();
        __syncthreads();

        const float* Ap = sm + s*STG;
        const float* Bp = sm + 2*STG + s*STG;
        #pragma unroll
        for (int ks = 0; ks < 4; ks++) {
            int k = ks*8;
            uint32_t af[4][4], bf[4][2];
            #pragma unroll
            for (int tm = 0; tm < 4; tm++) {
                const float* p = Ap + (wm*64 + tm*16 + g)*PAD + k + ct;
                af[tm][0] = __float_as_uint(p[0]);
                af[tm][1] = __float_as_uint(p[8*PAD]);
                af[tm][2] = __float_as_uint(p[4]);
                af[tm][3] = __float_as_uint(p[8*PAD + 4]);
            }
            #pragma unroll
            for (int tn = 0; tn < 4; tn++) {
                const float* p = Bp + (wn*32 + tn*8 + g)*PAD + k + ct;
                bf[tn][0] = __float_as_uint(p[0]);
                bf[tn][1] = __float_as_uint(p[4]);
            }
            #pragma unroll
            for (int tm = 0; tm < 4; tm++)
                #pragma unroll
                for (int tn = 0; tn < 4; tn++)
                    mma_tf32(acc[tm][tn], af[tm][0], af[tm][1], af[tm][2], af[tm][3],
                             bf[tn][0], bf[tn][1]);
        }
        __syncthreads();
        if (t + 2 < T) FILL(t + 2, s);
    }
    #undef FILL

    // ---- epilogue ----
    #pragma unroll
    for (int tm = 0; tm < 4; tm++) {
        int r0 = bm + wm*64 + tm*16 + g;
        #pragma unroll
        for (int half = 0; half < 2; half++) {
            int r = r0 + half*8;
            size_t dst = r;
            if (MODE == 2) {
                int widx = r >> 6, n = r & 63;
                int bb2 = widx >> 6, wi = widx & 63;
                int wy = wi >> 3, wx = wi & 7;
                int iy = n >> 3,  ix = n & 7;
                int dh = (wy*8 + iy + SSZ) & 63;
                int dw = (wx*8 + ix + SSZ) & 63;
                dst = (size_t)(bb2*4096 + dh*64 + dw);
            }
            #pragma unroll
            for (int tn = 0; tn < 4; tn++) {
                int col = bn + wn*32 + tn*8 + ct*2;
                float v0 = acc[tm][tn][half*2]     + bias[col];
                float v1 = acc[tm][tn][half*2 + 1] + bias[col + 1];
                if (MODE == 1) {
                    v0 = tf32r(0.5f * v0 * (1.f + erff(v0 * 0.7071067811865475f)));
                    v1 = tf32r(0.5f * v1 * (1.f + erff(v1 * 0.7071067811865475f)));
                }
                if (MODE >= 2) {
                    const float2 rr = *(const float2*)(res + dst*(size_t)N + col);
                    v0 += rr.x; v1 += rr.y;
                }
                *(float2*)(C + dst*(size_t)N + col) = make_float2(v0, v1);
            }
        }
    }
}

// ---------------- windowed attention: one block per (window, head) --------------
__global__ void attn_kernel(const float* __restrict__ qkv, const float* __restrict__ rpb,
                            float* __restrict__ out)
{
    int bid  = blockIdx.x;      // widx*8 + head
    int head = bid & 7;
    int widx = bid >> 3;
    int wi = widx & 63;
    int wy = wi >> 3, wx = wi & 7;

    __shared__ float qs[64][33];
    __shared__ float ks[64][33];
    __shared__ float vs[64][33];
    __shared__ float sc[64][65];
    __shared__ int   regid[64];

    int tid = threadIdx.x;      // 0..255
    for (int idx = tid; idx < 2048; idx += 256) {
        int n = idx >> 5, d = idx & 31;
        size_t base = (size_t)(widx*64 + n) * (3*DIMC) + head*32 + d;
        qs[n][d] = qkv[base]           * QSCALE;
        ks[n][d] = qkv[base + DIMC];
        vs[n][d] = qkv[base + 2*DIMC];
    }
    if (tid < 64) {
        int iy = tid >> 3, ix = tid & 7;
        int rh = (wy < 7) ? 0 : ((iy < SSZ) ? 1 : 2);
        int rw = (wx < 7) ? 0 : ((ix < SSZ) ? 1 : 2);
        regid[tid] = rh*3 + rw;
    }
    __syncthreads();

    int ty = tid >> 4, tx = tid & 15;
    int p0 = ty * 4;
    float s[4][4];
    #pragma unroll
    for (int i = 0; i < 4; i++)
        #pragma unroll
        for (int j = 0; j < 4; j++) s[i][j] = 0.f;

    #pragma unroll 8
    for (int d = 0; d < 32; d++) {
        float a[4], b[4];
        #pragma unroll
        for (int i = 0; i < 4; i++) a[i] = qs[p0+i][d];
        #pragma unroll
        for (int j = 0; j < 4; j++) b[j] = ks[tx + 16*j][d];
        #pragma unroll
        for (int i = 0; i < 4; i++)
            #pragma unroll
            for (int j = 0; j < 4; j++) s[i][j] += a[i]*b[j];
    }
    #pragma unroll
    for (int i = 0; i < 4; i++) {
        int p = p0 + i;
        #pragma unroll
        for (int j = 0; j < 4; j++) {
            int q = tx + 16*j;
            int dx = (p & 7) - (q & 7);
            int dy = (p >> 3) - (q >> 3);
            int rpi = (dx + 7)*15 + (dy + 7);
            float v = s[i][j] + __ldg(&rpb[rpi*HEADS + head]);
            if (regid[p] == regid[q]) v -= 100.f;
            sc[p][q] = v;
        }
    }
    __syncthreads();

    if (tid < 64) {
        float mx = -1e30f;
        #pragma unroll 8
        for (int q = 0; q < 64; q++) mx = fmaxf(mx, sc[tid][q]);
        float sum = 0.f;
        #pragma unroll 8
        for (int q = 0; q < 64; q++) {
            float e = __expf(sc[tid][q] - mx);
            sc[tid][q] = e;
            sum += e;
        }
        float inv = 1.f / sum;
        #pragma unroll 8
        for (int q = 0; q < 64; q++) sc[tid][q] *= inv;
    }
    __syncthreads();

    int d0  = (tid & 15) * 2;
    int pp0 = (tid >> 4) * 4;
    float o[4][2];
    #pragma unroll
    for (int i = 0; i < 4; i++) { o[i][0] = 0.f; o[i][1] = 0.f; }
    #pragma unroll 8
    for (int kk = 0; kk < 64; kk++) {
        float b0 = vs[kk][d0], b1 = vs[kk][d0+1];
        #pragma unroll
        for (int i = 0; i < 4; i++) {
            float a = sc[pp0+i][kk];
            o[i][0] += a*b0;
            o[i][1] += a*b1;
        }
    }
    #pragma unroll
    for (int i = 0; i < 4; i++) {
        size_t row = (size_t)(widx*64 + pp0 + i);
        out[row*DIMC + head*32 + d0    ] = tf32r(o[i][0]);
        out[row*DIMC + head*32 + d0 + 1] = tf32r(o[i][1]);
    }
}

// ---------------------------------- launch --------------------------------------
extern "C" void kernel_launch(void* const* d_in, const int* in_sizes, int n_in,
                              void* d_out, int out_size)
{
    const float* x      = (const float*)d_in[0];
    const float* n1g    = (const float*)d_in[1];
    const float* n1b    = (const float*)d_in[2];
    const float* qkv_w  = (const float*)d_in[3];
    const float* qkv_b  = (const float*)d_in[4];
    const float* rpb    = (const float*)d_in[5];
    const float* proj_w = (const float*)d_in[6];
    const float* proj_b = (const float*)d_in[7];
    const float* n2g    = (const float*)d_in[8];
    const float* n2b    = (const float*)d_in[9];
    const float* fc1_w  = (const float*)d_in[10];
    const float* fc1_b  = (const float*)d_in[11];
    const float* fc2_w  = (const float*)d_in[12];
    const float* fc2_b  = (const float*)d_in[13];
    float* out = (float*)d_out;

    float *xw, *qkvbuf, *attn, *y, *yn, *m1;
    float *wt_qkv, *wt_proj, *wt_fc1, *wt_fc2;
    cudaGetSymbolAddress((void**)&xw,      g_xw);
    cudaGetSymbolAddress((void**)&qkvbuf,  g_qkv);
    cudaGetSymbolAddress((void**)&attn,    g_attn);
    cudaGetSymbolAddress((void**)&y,       g_y);
    cudaGetSymbolAddress((void**)&yn,      g_yn);
    cudaGetSymbolAddress((void**)&m1,      g_m1);
    cudaGetSymbolAddress((void**)&wt_qkv,  g_wt_qkv);
    cudaGetSymbolAddress((void**)&wt_proj, g_wt_proj);
    cudaGetSymbolAddress((void**)&wt_fc1,  g_wt_fc1);
    cudaGetSymbolAddress((void**)&wt_fc2,  g_wt_fc2);

    const int SMEM = 4 * STG * sizeof(float);   // 73728 B
    cudaFuncSetAttribute(mma_gemm<0>, cudaFuncAttributeMaxDynamicSharedMemorySize, SMEM);
    cudaFuncSetAttribute(mma_gemm<1>, cudaFuncAttributeMaxDynamicSharedMemorySize, SMEM);
    cudaFuncSetAttribute(mma_gemm<2>, cudaFuncAttributeMaxDynamicSharedMemorySize, SMEM);
    cudaFuncSetAttribute(mma_gemm<3>, cudaFuncAttributeMaxDynamicSharedMemorySize, SMEM);

    dim3 t32(32, 8);
    // weight transposes (cheap; weights L2-resident afterwards)
    transpose_kernel<<<dim3(768/32, 256/32),  t32>>>(qkv_w,  wt_qkv,  256, 768);
    transpose_kernel<<<dim3(256/32, 256/32),  t32>>>(proj_w, wt_proj, 256, 256);
    transpose_kernel<<<dim3(1024/32, 256/32), t32>>>(fc1_w,  wt_fc1,  256, 1024);
    transpose_kernel<<<dim3(256/32, 1024/32), t32>>>(fc2_w,  wt_fc2,  1024, 256);

    // 1) LN1 + cyclic shift + window partition (tf32-rounded)
    ln_kernel<<<ROWS, 256>>>(x, n1g, n1b, xw, 1);
    // 2) QKV GEMM: [65536,256] @ [256,768]
    mma_gemm<0><<<dim3(768/128, ROWS/128), 256, SMEM>>>(xw, wt_qkv, qkv_b, nullptr, qkvbuf,
                                                        ROWS, 768, 256);
    // 3) windowed attention (fp32; writes tf32-rounded output)
    attn_kernel<<<ROWS/64*HEADS, 256>>>(qkvbuf, rpb, attn);
    // 4) proj GEMM + window-reverse/shift scatter + residual(x) -> y
    mma_gemm<2><<<dim3(256/128, ROWS/128), 256, SMEM>>>(attn, wt_proj, proj_b, x, y,
                                                        ROWS, 256, 256);
    // 5) LN2 (tf32-rounded)
    ln_kernel<<<ROWS, 256>>>(y, n2g, n2b, yn, 0);
    // 6) fc1 + exact GELU (tf32-rounded output)
    mma_gemm<1><<<dim3(1024/128, ROWS/128), 256, SMEM>>>(yn, wt_fc1, fc1_b, nullptr, m1,
                                                         ROWS, 1024, 256);
    // 7) fc2 + residual with ORIGINAL shortcut x -> out
    mma_gemm<3><<<dim3(256/128, ROWS/128), 256, SMEM>>>(m1, wt_fc2, fc2_b, x, out,
                                                        ROWS, 256, 1024);
}

// round 4
// speedup vs baseline: 3.6364x; 1.4067x over previous
#include <cuda_runtime.h>
#include <cuda_bf16.h>
#include <math.h>
#include <cstdint>

#define DIMC 256
#define HEADS 8
#define WSZ 8
#define SSZ 4
#define BATCH 16
#define IMG 64
#define ROWS (BATCH*IMG*IMG)   /* 65536 token rows */
#define QSCALE 0.17677669529663687f

typedef __nv_bfloat16 bf16;

// ---------------- scratch (device globals; no allocation allowed) ----------------
__device__ __align__(16) bf16  g_xw  [ROWS*DIMC];      // LN1 + shift + window partition
__device__ __align__(16) bf16  g_qkv [ROWS*3*DIMC];    // qkv projections
__device__ __align__(16) bf16  g_attn[ROWS*DIMC];      // attention output (window layout)
__device__ __align__(16) float g_y   [ROWS*DIMC];      // x + proj (natural layout, fp32)
__device__ __align__(16) bf16  g_yn  [ROWS*DIMC];      // LN2(y)
__device__ __align__(16) bf16  g_m1  [ROWS*4*DIMC];    // gelu(fc1)
// transposed weights  WT[n*K + k] = W[k*N + n]   (bf16)
__device__ __align__(16) bf16 g_wt_qkv [768*256];
__device__ __align__(16) bf16 g_wt_proj[256*256];
__device__ __align__(16) bf16 g_wt_fc1 [1024*256];
__device__ __align__(16) bf16 g_wt_fc2 [256*1024];

// ---------------- helpers --------------------------------------------------------
__device__ __forceinline__ uint32_t smem_u32(const void* p) {
    uint32_t a;
    asm("{ .reg .u64 t; cvta.to.shared.u64 t, %1; cvt.u32.u64 %0, t; }" : "=r"(a) : "l"(p));
    return a;
}
#define CP_ASYNC16(dst, src) \
    asm volatile("cp.async.cg.shared.global [%0], [%1], 16;" :: "r"(dst), "l"(src))
#define CP_COMMIT() asm volatile("cp.async.commit_group;")
#define CP_WAIT2()  asm volatile("cp.async.wait_group 2;")
#define CP_WAIT1()  asm volatile("cp.async.wait_group 1;")
#define CP_WAIT0()  asm volatile("cp.async.wait_group 0;")

__device__ __forceinline__ void mma_bf16(float c[4], uint32_t a0, uint32_t a1,
                                         uint32_t a2, uint32_t a3,
                                         uint32_t b0, uint32_t b1) {
    asm volatile(
        "mma.sync.aligned.m16n8k16.row.col.f32.bf16.bf16.f32 "
        "{%0,%1,%2,%3}, {%4,%5,%6,%7}, {%8,%9}, {%0,%1,%2,%3};"
        : "+f"(c[0]), "+f"(c[1]), "+f"(c[2]), "+f"(c[3])
        : "r"(a0), "r"(a1), "r"(a2), "r"(a3), "r"(b0), "r"(b1));
}

// ---------------- LayerNorm: one warp per row, float4 loads, bf16 out -----------
__global__ void ln_kernel(const float* __restrict__ in, const float* __restrict__ g,
                          const float* __restrict__ b, bf16* __restrict__ out,
                          int shiftmode)
{
    int o = (blockIdx.x * blockDim.x + threadIdx.x) >> 5;   // row
    int lane = threadIdx.x & 31;
    int src = o;
    if (shiftmode) {
        int widx = o >> 6, n = o & 63;
        int bb = widx >> 6, wi = widx & 63;
        int wy = wi >> 3, wx = wi & 7;
        int iy = n >> 3,  ix = n & 7;
        int sh = (wy*8 + iy + SSZ) & 63;
        int sw = (wx*8 + ix + SSZ) & 63;
        src = bb*4096 + sh*64 + sw;
    }
    const float4* p = (const float4*)(in + (size_t)src*DIMC + lane*8);
    float4 v0 = p[0], v1 = p[1];
    float s  = v0.x+v0.y+v0.z+v0.w + v1.x+v1.y+v1.z+v1.w;
    float s2 = v0.x*v0.x+v0.y*v0.y+v0.z*v0.z+v0.w*v0.w
             + v1.x*v1.x+v1.y*v1.y+v1.z*v1.z+v1.w*v1.w;
    #pragma unroll
    for (int off = 16; off; off >>= 1) {
        s  += __shfl_xor_sync(0xffffffffu, s,  off);
        s2 += __shfl_xor_sync(0xffffffffu, s2, off);
    }
    float mean = s * (1.f/DIMC);
    float var  = s2 * (1.f/DIMC) - mean*mean;
    float r = rsqrtf(var + 1e-5f);
    const float4* gp = (const float4*)(g + lane*8);
    const float4* bp = (const float4*)(b + lane*8);
    float4 g0 = gp[0], g1 = gp[1], b0 = bp[0], b1 = bp[1];
    union { uint4 u; bf16 h[8]; } res;
    res.h[0] = __float2bfloat16((v0.x-mean)*r*g0.x + b0.x);
    res.h[1] = __float2bfloat16((v0.y-mean)*r*g0.y + b0.y);
    res.h[2] = __float2bfloat16((v0.z-mean)*r*g0.z + b0.z);
    res.h[3] = __float2bfloat16((v0.w-mean)*r*g0.w + b0.w);
    res.h[4] = __float2bfloat16((v1.x-mean)*r*g1.x + b1.x);
    res.h[5] = __float2bfloat16((v1.y-mean)*r*g1.y + b1.y);
    res.h[6] = __float2bfloat16((v1.z-mean)*r*g1.z + b1.z);
    res.h[7] = __float2bfloat16((v1.w-mean)*r*g1.w + b1.w);
    *(uint4*)(out + (size_t)o*DIMC + lane*8) = res.u;
}

// ---------------- weight transpose (+ bf16 round): WT[n*K+k] = W[k*N+n] --------
__global__ void transpose_kernel(const float* __restrict__ w, bf16* __restrict__ wt,
                                 int K, int N)
{
    __shared__ float t[32][33];
    int k0 = blockIdx.y*32, n0 = blockIdx.x*32;
    int tx = threadIdx.x, ty = threadIdx.y;   // 32 x 8
    #pragma unroll
    for (int i = ty; i < 32; i += 8) t[i][tx] = w[(size_t)(k0+i)*N + n0 + tx];
    __syncthreads();
    #pragma unroll
    for (int i = ty; i < 32; i += 8)
        wt[(size_t)(n0+i)*K + k0 + tx] = __float2bfloat16(t[tx][i]);
}

// ============ bf16 mma.sync GEMM: 128x128x32 tiles, 4-stage cp.async ============
// D[M,N] = A[M,K] @ B[K,N]  (B supplied transposed: BT[N,K]); bf16 in, fp32 accum.
// MODE 0: bf16(+bias)    MODE 1: bf16(gelu(+bias))
// MODE 2: f32: scatter(window-reverse+shift)+res+bias    MODE 3: f32: res+bias
#define PADH 40                      /* halves per 32-half row in smem */
#define ASTG (128*PADH*2)            /* bytes per stage per operand = 10240 */
template<int MODE, typename OutT>
__global__ __launch_bounds__(256, 2)
void mma_gemm(const bf16* __restrict__ A, const bf16* __restrict__ BT,
              const float* __restrict__ bias, const float* __restrict__ res,
              OutT* __restrict__ C, int M, int N, int K)
{
    extern __shared__ char smem[];   // A stages [0..3] | B stages [0..3]
    int tid = threadIdx.x, wid = tid >> 5, lane = tid & 31;
    int g = lane >> 2, ct = lane & 3;
    int wm = wid & 1, wn = wid >> 1;          // 2 x 4 warp grid
    int bm = blockIdx.y * 128, bn = blockIdx.x * 128;
    const bf16* Ab = A  + (size_t)bm * K;
    const bf16* Bb = BT + (size_t)bn * K;
    const int T = K / 32;

    int f_row = tid >> 1;
    int f_cb  = (tid & 1) * 2;

    #define FILL(t, s) do { \
        char* as_ = smem + (s)*ASTG; \
        char* bs_ = smem + 4*ASTG + (s)*ASTG; \
        _Pragma("unroll") \
        for (int i = 0; i < 2; i++) { \
            int c = f_cb + i; \
            CP_ASYNC16(smem_u32(as_ + f_row*(PADH*2) + c*16), \
                       Ab + (size_t)f_row*K + (t)*32 + c*8); \
            CP_ASYNC16(smem_u32(bs_ + f_row*(PADH*2) + c*16), \
                       Bb + (size_t)f_row*K + (t)*32 + c*8); \
        } \
        CP_COMMIT(); \
    } while (0)

    float acc[4][4][4];
    #pragma unroll
    for (int i = 0; i < 4; i++)
        #pragma unroll
        for (int j = 0; j < 4; j++)
            #pragma unroll
            for (int e = 0; e < 4; e++) acc[i][j][e] = 0.f;

    FILL(0, 0); FILL(1, 1); FILL(2, 2);

    for (int t = 0; t < T; t++) {
        int rem = T - 1 - t;
        if (rem >= 2) CP_WAIT2(); else if (rem == 1) CP_WAIT1(); else CP_WAIT0();
        __syncthreads();
        if (t + 3 < T) FILL(t + 3, (t + 3) & 3);

        int s = t & 3;
        const bf16* Ap = (const bf16*)(smem + s*ASTG);
        const bf16* Bp = (const bf16*)(smem + 4*ASTG + s*ASTG);
        #pragma unroll
        for (int ks = 0; ks < 2; ks++) {
            int k = ks*16;
            uint32_t af[4][4], bfr[4][2];
            #pragma unroll
            for (int tm = 0; tm < 4; tm++) {
                const bf16* p = Ap + (wm*64 + tm*16 + g)*PADH + k + ct*2;
                af[tm][0] = *(const uint32_t*)p;
                af[tm][1] = *(const uint32_t*)(p + 8*PADH);
                af[tm][2] = *(const uint32_t*)(p + 8);
                af[tm][3] = *(const uint32_t*)(p + 8*PADH + 8);
            }
            #pragma unroll
            for (int tn = 0; tn < 4; tn++) {
                const bf16* p = Bp + (wn*32 + tn*8 + g)*PADH + k + ct*2;
                bfr[tn][0] = *(const uint32_t*)p;
                bfr[tn][1] = *(const uint32_t*)(p + 8);
            }
            #pragma unroll
            for (int tm = 0; tm < 4; tm++)
                #pragma unroll
                for (int tn = 0; tn < 4; tn++)
                    mma_bf16(acc[tm][tn], af[tm][0], af[tm][1], af[tm][2], af[tm][3],
                             bfr[tn][0], bfr[tn][1]);
        }
        __syncthreads();
    }
    #undef FILL

    // ---- epilogue ----
    #pragma unroll
    for (int tm = 0; tm < 4; tm++) {
        int r0 = bm + wm*64 + tm*16 + g;
        #pragma unroll
        for (int half = 0; half < 2; half++) {
            int r = r0 + half*8;
            size_t dst = r;
            if (MODE == 2) {
                int widx = r >> 6, n = r & 63;
                int bb2 = widx >> 6, wi = widx & 63;
                int wy = wi >> 3, wx = wi & 7;
                int iy = n >> 3,  ix = n & 7;
                int dh = (wy*8 + iy + SSZ) & 63;
                int dw = (wx*8 + ix + SSZ) & 63;
                dst = (size_t)(bb2*4096 + dh*64 + dw);
            }
            #pragma unroll
            for (int tn = 0; tn < 4; tn++) {
                int col = bn + wn*32 + tn*8 + ct*2;
                float v0 = acc[tm][tn][half*2]     + bias[col];
                float v1 = acc[tm][tn][half*2 + 1] + bias[col + 1];
                if (MODE == 1) {
                    v0 = 0.5f * v0 * (1.f + erff(v0 * 0.7071067811865475f));
                    v1 = 0.5f * v1 * (1.f + erff(v1 * 0.7071067811865475f));
                }
                if (MODE >= 2) {
                    const float2 rr = *(const float2*)(res + dst*(size_t)N + col);
                    v0 += rr.x; v1 += rr.y;
                    *(float2*)((float*)C + dst*(size_t)N + col) = make_float2(v0, v1);
                } else {
                    __nv_bfloat162 h = __floats2bfloat162_rn(v0, v1);
                    *(__nv_bfloat162*)((bf16*)C + dst*(size_t)N + col) = h;
                }
            }
        }
    }
}

// ---------------- windowed attention: one block per (window, head) --------------
__global__ void attn_kernel(const bf16* __restrict__ qkv, const float* __restrict__ rpb,
                            bf16* __restrict__ out)
{
    int bid  = blockIdx.x;      // widx*8 + head
    int head = bid & 7;
    int widx = bid >> 3;
    int wi = widx & 63;
    int wy = wi >> 3, wx = wi & 7;

    __shared__ float qs[64][33];
    __shared__ float ks[64][33];
    __shared__ float vs[64][33];
    __shared__ float sc[64][65];
    __shared__ int   regid[64];

    int tid = threadIdx.x;      // 0..255
    for (int idx = tid; idx < 2048; idx += 256) {
        int n = idx >> 5, d = idx & 31;
        size_t base = (size_t)(widx*64 + n) * (3*DIMC) + head*32 + d;
        qs[n][d] = __bfloat162float(qkv[base])        * QSCALE;
        ks[n][d] = __bfloat162float(qkv[base + DIMC]);
        vs[n][d] = __bfloat162float(qkv[base + 2*DIMC]);
    }
    if (tid < 64) {
        int iy = tid >> 3, ix = tid & 7;
        int rh = (wy < 7) ? 0 : ((iy < SSZ) ? 1 : 2);
        int rw = (wx < 7) ? 0 : ((ix < SSZ) ? 1 : 2);
        regid[tid] = rh*3 + rw;
    }
    __syncthreads();

    int ty = tid >> 4, tx = tid & 15;
    int p0 = ty * 4;
    float s[4][4];
    #pragma unroll
    for (int i = 0; i < 4; i++)
        #pragma unroll
        for (int j = 0; j < 4; j++) s[i][j] = 0.f;

    #pragma unroll 8
    for (int d = 0; d < 32; d++) {
        float a[4], b[4];
        #pragma unroll
        for (int i = 0; i < 4; i++) a[i] = qs[p0+i][d];
        #pragma unroll
        for (int j = 0; j < 4; j++) b[j] = ks[tx + 16*j][d];
        #pragma unroll
        for (int i = 0; i < 4; i++)
            #pragma unroll
            for (int j = 0; j < 4; j++) s[i][j] += a[i]*b[j];
    }
    #pragma unroll
    for (int i = 0; i < 4; i++) {
        int p = p0 + i;
        #pragma unroll
        for (int j = 0; j < 4; j++) {
            int q = tx + 16*j;
            int dx = (p & 7) - (q & 7);
            int dy = (p >> 3) - (q >> 3);
            int rpi = (dx + 7)*15 + (dy + 7);
            float v = s[i][j] + __ldg(&rpb[rpi*HEADS + head]);
            if (regid[p] == regid[q]) v -= 100.f;
            sc[p][q] = v;
        }
    }
    __syncthreads();

    if (tid < 64) {
        float mx = -1e30f;
        #pragma unroll 8
        for (int q = 0; q < 64; q++) mx = fmaxf(mx, sc[tid][q]);
        float sum = 0.f;
        #pragma unroll 8
        for (int q = 0; q < 64; q++) {
            float e = __expf(sc[tid][q] - mx);
            sc[tid][q] = e;
            sum += e;
        }
        float inv = 1.f / sum;
        #pragma unroll 8
        for (int q = 0; q < 64; q++) sc[tid][q] *= inv;
    }
    __syncthreads();

    int d0  = (tid & 15) * 2;
    int pp0 = (tid >> 4) * 4;
    float o[4][2];
    #pragma unroll
    for (int i = 0; i < 4; i++) { o[i][0] = 0.f; o[i][1] = 0.f; }
    #pragma unroll 8
    for (int kk = 0; kk < 64; kk++) {
        float b0 = vs[kk][d0], b1 = vs[kk][d0+1];
        #pragma unroll
        for (int i = 0; i < 4; i++) {
            float a = sc[pp0+i][kk];
            o[i][0] += a*b0;
            o[i][1] += a*b1;
        }
    }
    #pragma unroll
    for (int i = 0; i < 4; i++) {
        size_t row = (size_t)(widx*64 + pp0 + i);
        *(__nv_bfloat162*)(out + row*DIMC + head*32 + d0) =
            __floats2bfloat162_rn(o[i][0], o[i][1]);
    }
}

// ---------------------------------- launch --------------------------------------
extern "C" void kernel_launch(void* const* d_in, const int* in_sizes, int n_in,
                              void* d_out, int out_size)
{
    const float* x      = (const float*)d_in[0];
    const float* n1g    = (const float*)d_in[1];
    const float* n1b    = (const float*)d_in[2];
    const float* qkv_w  = (const float*)d_in[3];
    const float* qkv_b  = (const float*)d_in[4];
    const float* rpb    = (const float*)d_in[5];
    const float* proj_w = (const float*)d_in[6];
    const float* proj_b = (const float*)d_in[7];
    const float* n2g    = (const float*)d_in[8];
    const float* n2b    = (const float*)d_in[9];
    const float* fc1_w  = (const float*)d_in[10];
    const float* fc1_b  = (const float*)d_in[11];
    const float* fc2_w  = (const float*)d_in[12];
    const float* fc2_b  = (const float*)d_in[13];
    float* out = (float*)d_out;

    bf16 *xw, *qkvbuf, *attn, *yn, *m1;
    float *y;
    bf16 *wt_qkv, *wt_proj, *wt_fc1, *wt_fc2;
    cudaGetSymbolAddress((void**)&xw,      g_xw);
    cudaGetSymbolAddress((void**)&qkvbuf,  g_qkv);
    cudaGetSymbolAddress((void**)&attn,    g_attn);
    cudaGetSymbolAddress((void**)&y,       g_y);
    cudaGetSymbolAddress((void**)&yn,      g_yn);
    cudaGetSymbolAddress((void**)&m1,      g_m1);
    cudaGetSymbolAddress((void**)&wt_qkv,  g_wt_qkv);
    cudaGetSymbolAddress((void**)&wt_proj, g_wt_proj);
    cudaGetSymbolAddress((void**)&wt_fc1,  g_wt_fc1);
    cudaGetSymbolAddress((void**)&wt_fc2,  g_wt_fc2);

    const int SMEM = 8 * ASTG;   // 81920 B
    cudaFuncSetAttribute((mma_gemm<0, bf16>),  cudaFuncAttributeMaxDynamicSharedMemorySize, SMEM);
    cudaFuncSetAttribute((mma_gemm<1, bf16>),  cudaFuncAttributeMaxDynamicSharedMemorySize, SMEM);
    cudaFuncSetAttribute((mma_gemm<2, float>), cudaFuncAttributeMaxDynamicSharedMemorySize, SMEM);
    cudaFuncSetAttribute((mma_gemm<3, float>), cudaFuncAttributeMaxDynamicSharedMemorySize, SMEM);

    dim3 t32(32, 8);
    // weight transposes (cheap; weights L2-resident afterwards)
    transpose_kernel<<<dim3(768/32, 256/32),  t32>>>(qkv_w,  wt_qkv,  256, 768);
    transpose_kernel<<<dim3(256/32, 256/32),  t32>>>(proj_w, wt_proj, 256, 256);
    transpose_kernel<<<dim3(1024/32, 256/32), t32>>>(fc1_w,  wt_fc1,  256, 1024);
    transpose_kernel<<<dim3(256/32, 1024/32), t32>>>(fc2_w,  wt_fc2,  1024, 256);

    // 1) LN1 + cyclic shift + window partition (bf16 out)
    ln_kernel<<<ROWS/8, 256>>>(x, n1g, n1b, xw, 1);
    // 2) QKV GEMM: [65536,256] @ [256,768] -> bf16
    mma_gemm<0, bf16><<<dim3(768/128, ROWS/128), 256, SMEM>>>(xw, wt_qkv, qkv_b, nullptr,
                                                              qkvbuf, ROWS, 768, 256);
    // 3) windowed attention -> bf16
    attn_kernel<<<ROWS/64*HEADS, 256>>>(qkvbuf, rpb, attn);
    // 4) proj GEMM + window-reverse/shift scatter + residual(x) -> y (fp32)
    mma_gemm<2, float><<<dim3(256/128, ROWS/128), 256, SMEM>>>(attn, wt_proj, proj_b, x,
                                                               y, ROWS, 256, 256);
    // 5) LN2 (bf16 out)
    ln_kernel<<<ROWS/8, 256>>>(y, n2g, n2b, yn, 0);
    // 6) fc1 + exact GELU -> bf16
    mma_gemm<1, bf16><<<dim3(1024/128, ROWS/128), 256, SMEM>>>(yn, wt_fc1, fc1_b, nullptr,
                                                               m1, ROWS, 1024, 256);
    // 7) fc2 + residual with ORIGINAL shortcut x -> out (fp32)
    mma_gemm<3, float><<<dim3(256/128, ROWS/128), 256, SMEM>>>(m1, wt_fc2, fc2_b, x,
                                                               out, ROWS, 256, 1024);
}

// round 5
// speedup vs baseline: 4.5374x; 1.2478x over previous
#include <cuda_runtime.h>
#include <cuda_bf16.h>
#include <math.h>
#include <cstdint>

#define DIMC 256
#define HEADS 8
#define WSZ 8
#define SSZ 4
#define BATCH 16
#define IMG 64
#define ROWS (BATCH*IMG*IMG)   /* 65536 token rows */
#define QSCALE 0.17677669529663687f

typedef __nv_bfloat16 bf16;

// ---------------- scratch (device globals; no allocation allowed) ----------------
__device__ __align__(16) bf16  g_xw  [ROWS*DIMC];      // LN1 + shift + window partition
__device__ __align__(16) bf16  g_qkv [ROWS*3*DIMC];    // qkv projections
__device__ __align__(16) bf16  g_attn[ROWS*DIMC];      // attention output (window layout)
__device__ __align__(16) float g_y   [ROWS*DIMC];      // x + proj (natural layout, fp32)
__device__ __align__(16) bf16  g_yn  [ROWS*DIMC];      // LN2(y)
__device__ __align__(16) bf16  g_m1  [ROWS*4*DIMC];    // gelu(fc1)
// transposed weights  WT[n*K + k] = W[k*N + n]   (bf16)
__device__ __align__(16) bf16 g_wt_qkv [768*256];
__device__ __align__(16) bf16 g_wt_proj[256*256];
__device__ __align__(16) bf16 g_wt_fc1 [1024*256];
__device__ __align__(16) bf16 g_wt_fc2 [256*1024];

// ---------------- helpers --------------------------------------------------------
__device__ __forceinline__ uint32_t smem_u32(const void* p) {
    uint32_t a;
    asm("{ .reg .u64 t; cvta.to.shared.u64 t, %1; cvt.u32.u64 %0, t; }" : "=r"(a) : "l"(p));
    return a;
}
#define CP_ASYNC16(dst, src) \
    asm volatile("cp.async.cg.shared.global [%0], [%1], 16;" :: "r"(dst), "l"(src))
#define CP_COMMIT() asm volatile("cp.async.commit_group;")
#define CP_WAIT2()  asm volatile("cp.async.wait_group 2;")
#define CP_WAIT1()  asm volatile("cp.async.wait_group 1;")
#define CP_WAIT0()  asm volatile("cp.async.wait_group 0;")

__device__ __forceinline__ void mma_bf16(float c[4], uint32_t a0, uint32_t a1,
                                         uint32_t a2, uint32_t a3,
                                         uint32_t b0, uint32_t b1) {
    asm volatile(
        "mma.sync.aligned.m16n8k16.row.col.f32.bf16.bf16.f32 "
        "{%0,%1,%2,%3}, {%4,%5,%6,%7}, {%8,%9}, {%0,%1,%2,%3};"
        : "+f"(c[0]), "+f"(c[1]), "+f"(c[2]), "+f"(c[3])
        : "r"(a0), "r"(a1), "r"(a2), "r"(a3), "r"(b0), "r"(b1));
}
__device__ __forceinline__ void ldmat_x4(uint32_t r[4], uint32_t saddr) {
    asm volatile("ldmatrix.sync.aligned.m8n8.x4.shared.b16 {%0,%1,%2,%3}, [%4];"
                 : "=r"(r[0]), "=r"(r[1]), "=r"(r[2]), "=r"(r[3]) : "r"(saddr));
}
__device__ __forceinline__ uint32_t pack_bf16x2(float lo, float hi) {
    __nv_bfloat162 h = __floats2bfloat162_rn(lo, hi);
    return *(uint32_t*)&h;
}

// ---------------- LayerNorm: one warp per row, float4 loads, bf16 out -----------
__global__ void ln_kernel(const float* __restrict__ in, const float* __restrict__ g,
                          const float* __restrict__ b, bf16* __restrict__ out,
                          int shiftmode)
{
    int o = (blockIdx.x * blockDim.x + threadIdx.x) >> 5;   // row
    int lane = threadIdx.x & 31;
    int src = o;
    if (shiftmode) {
        int widx = o >> 6, n = o & 63;
        int bb = widx >> 6, wi = widx & 63;
        int wy = wi >> 3, wx = wi & 7;
        int iy = n >> 3,  ix = n & 7;
        int sh = (wy*8 + iy + SSZ) & 63;
        int sw = (wx*8 + ix + SSZ) & 63;
        src = bb*4096 + sh*64 + sw;
    }
    const float4* p = (const float4*)(in + (size_t)src*DIMC + lane*8);
    float4 v0 = p[0], v1 = p[1];
    float s  = v0.x+v0.y+v0.z+v0.w + v1.x+v1.y+v1.z+v1.w;
    float s2 = v0.x*v0.x+v0.y*v0.y+v0.z*v0.z+v0.w*v0.w
             + v1.x*v1.x+v1.y*v1.y+v1.z*v1.z+v1.w*v1.w;
    #pragma unroll
    for (int off = 16; off; off >>= 1) {
        s  += __shfl_xor_sync(0xffffffffu, s,  off);
        s2 += __shfl_xor_sync(0xffffffffu, s2, off);
    }
    float mean = s * (1.f/DIMC);
    float var  = s2 * (1.f/DIMC) - mean*mean;
    float r = rsqrtf(var + 1e-5f);
    const float4* gp = (const float4*)(g + lane*8);
    const float4* bp = (const float4*)(b + lane*8);
    float4 g0 = gp[0], g1 = gp[1], b0 = bp[0], b1 = bp[1];
    union { uint4 u; bf16 h[8]; } res;
    res.h[0] = __float2bfloat16((v0.x-mean)*r*g0.x + b0.x);
    res.h[1] = __float2bfloat16((v0.y-mean)*r*g0.y + b0.y);
    res.h[2] = __float2bfloat16((v0.z-mean)*r*g0.z + b0.z);
    res.h[3] = __float2bfloat16((v0.w-mean)*r*g0.w + b0.w);
    res.h[4] = __float2bfloat16((v1.x-mean)*r*g1.x + b1.x);
    res.h[5] = __float2bfloat16((v1.y-mean)*r*g1.y + b1.y);
    res.h[6] = __float2bfloat16((v1.z-mean)*r*g1.z + b1.z);
    res.h[7] = __float2bfloat16((v1.w-mean)*r*g1.w + b1.w);
    *(uint4*)(out + (size_t)o*DIMC + lane*8) = res.u;
}

// ---------------- weight transpose (+ bf16 round): WT[n*K+k] = W[k*N+n] --------
__global__ void transpose_kernel(const float* __restrict__ w, bf16* __restrict__ wt,
                                 int K, int N)
{
    __shared__ float t[32][33];
    int k0 = blockIdx.y*32, n0 = blockIdx.x*32;
    int tx = threadIdx.x, ty = threadIdx.y;   // 32 x 8
    #pragma unroll
    for (int i = ty; i < 32; i += 8) t[i][tx] = w[(size_t)(k0+i)*N + n0 + tx];
    __syncthreads();
    #pragma unroll
    for (int i = ty; i < 32; i += 8)
        wt[(size_t)(n0+i)*K + k0 + tx] = __float2bfloat16(t[tx][i]);
}

// ============ bf16 mma.sync GEMM: 128x128x32 tiles, 4-stage cp.async ============
// D[M,N] = A[M,K] @ B[K,N]  (B supplied transposed: BT[N,K]); bf16 in, fp32 accum.
// MODE 0: bf16(+bias)    MODE 1: bf16(gelu(+bias))
// MODE 2: f32: scatter(window-reverse+shift)+res+bias    MODE 3: f32: res+bias
#define PADH 40                      /* halves per 32-half row in smem */
#define ASTG (128*PADH*2)            /* bytes per stage per operand = 10240 */
template<int MODE, typename OutT>
__global__ __launch_bounds__(256, 2)
void mma_gemm(const bf16* __restrict__ A, const bf16* __restrict__ BT,
              const float* __restrict__ bias, const float* __restrict__ res,
              OutT* __restrict__ C, int M, int N, int K)
{
    extern __shared__ char smem[];   // A stages [0..3] | B stages [0..3]
    int tid = threadIdx.x, wid = tid >> 5, lane = tid & 31;
    int g = lane >> 2, ct = lane & 3;
    int wm = wid & 1, wn = wid >> 1;          // 2 x 4 warp grid
    int bm = blockIdx.y * 128, bn = blockIdx.x * 128;
    const bf16* Ab = A  + (size_t)bm * K;
    const bf16* Bb = BT + (size_t)bn * K;
    const int T = K / 32;

    int f_row = tid >> 1;
    int f_cb  = (tid & 1) * 2;

    #define FILL(t, s) do { \
        char* as_ = smem + (s)*ASTG; \
        char* bs_ = smem + 4*ASTG + (s)*ASTG; \
        _Pragma("unroll") \
        for (int i = 0; i < 2; i++) { \
            int c = f_cb + i; \
            CP_ASYNC16(smem_u32(as_ + f_row*(PADH*2) + c*16), \
                       Ab + (size_t)f_row*K + (t)*32 + c*8); \
            CP_ASYNC16(smem_u32(bs_ + f_row*(PADH*2) + c*16), \
                       Bb + (size_t)f_row*K + (t)*32 + c*8); \
        } \
        CP_COMMIT(); \
    } while (0)

    float acc[4][4][4];
    #pragma unroll
    for (int i = 0; i < 4; i++)
        #pragma unroll
        for (int j = 0; j < 4; j++)
            #pragma unroll
            for (int e = 0; e < 4; e++) acc[i][j][e] = 0.f;

    FILL(0, 0); FILL(1, 1); FILL(2, 2);

    // precomputed ldmatrix lane offsets (halves)
    int a_roff = (lane & 15);            // row within m16 tile
    int a_koff = (lane >> 4) * 8;        // k offset
    int b_roff = ((lane >> 4) & 1) * 8 + (lane & 7);
    int b_koff = ((lane >> 3) & 1) * 8;

    for (int t = 0; t < T; t++) {
        int rem = T - 1 - t;
        if (rem >= 2) CP_WAIT2(); else if (rem == 1) CP_WAIT1(); else CP_WAIT0();
        __syncthreads();
        if (t + 3 < T) FILL(t + 3, (t + 3) & 3);

        int s = t & 3;
        const bf16* Ap = (const bf16*)(smem + s*ASTG);
        const bf16* Bp = (const bf16*)(smem + 4*ASTG + s*ASTG);
        #pragma unroll
        for (int ks = 0; ks < 2; ks++) {
            int k = ks*16;
            uint32_t af[4][4], bfr[2][4];
            #pragma unroll
            for (int tm = 0; tm < 4; tm++)
                ldmat_x4(af[tm], smem_u32(Ap + (wm*64 + tm*16 + a_roff)*PADH + k + a_koff));
            #pragma unroll
            for (int tnp = 0; tnp < 2; tnp++)
                ldmat_x4(bfr[tnp], smem_u32(Bp + (wn*32 + tnp*16 + b_roff)*PADH + k + b_koff));
            #pragma unroll
            for (int tm = 0; tm < 4; tm++)
                #pragma unroll
                for (int tnp = 0; tnp < 2; tnp++) {
                    mma_bf16(acc[tm][2*tnp],   af[tm][0], af[tm][1], af[tm][2], af[tm][3],
                             bfr[tnp][0], bfr[tnp][1]);
                    mma_bf16(acc[tm][2*tnp+1], af[tm][0], af[tm][1], af[tm][2], af[tm][3],
                             bfr[tnp][2], bfr[tnp][3]);
                }
        }
        __syncthreads();
    }
    #undef FILL

    // ---- epilogue ----
    #pragma unroll
    for (int tm = 0; tm < 4; tm++) {
        int r0 = bm + wm*64 + tm*16 + g;
        #pragma unroll
        for (int half = 0; half < 2; half++) {
            int r = r0 + half*8;
            size_t dst = r;
            if (MODE == 2) {
                int widx = r >> 6, n = r & 63;
                int bb2 = widx >> 6, wi = widx & 63;
                int wy = wi >> 3, wx = wi & 7;
                int iy = n >> 3,  ix = n & 7;
                int dh = (wy*8 + iy + SSZ) & 63;
                int dw = (wx*8 + ix + SSZ) & 63;
                dst = (size_t)(bb2*4096 + dh*64 + dw);
            }
            #pragma unroll
            for (int tn = 0; tn < 4; tn++) {
                int col = bn + wn*32 + tn*8 + ct*2;
                float v0 = acc[tm][tn][half*2]     + bias[col];
                float v1 = acc[tm][tn][half*2 + 1] + bias[col + 1];
                if (MODE == 1) {
                    v0 = 0.5f * v0 * (1.f + erff(v0 * 0.7071067811865475f));
                    v1 = 0.5f * v1 * (1.f + erff(v1 * 0.7071067811865475f));
                }
                if (MODE >= 2) {
                    const float2 rr = *(const float2*)(res + dst*(size_t)N + col);
                    v0 += rr.x; v1 += rr.y;
                    *(float2*)((float*)C + dst*(size_t)N + col) = make_float2(v0, v1);
                } else {
                    __nv_bfloat162 h = __floats2bfloat162_rn(v0, v1);
                    *(__nv_bfloat162*)((bf16*)C + dst*(size_t)N + col) = h;
                }
            }
        }
    }
}

// ======== tensor-core windowed attention: block = (window, head), 4 warps =======
// Each warp: 16 query rows. QK^T and PV via bf16 mma; register softmax.
__global__ __launch_bounds__(128)
void attn_kernel(const bf16* __restrict__ qkv, const float* __restrict__ rpb,
                 bf16* __restrict__ out)
{
    int bid  = blockIdx.x;      // widx*8 + head
    int head = bid & 7;
    int widx = bid >> 3;
    int wi = widx & 63;
    int wy = wi >> 3, wx = wi & 7;

    __shared__ bf16 qs[64*40];      // [token][d pad 40]
    __shared__ bf16 ksm[64*40];
    __shared__ bf16 vt[32*72];      // [d][token pad 72]
    __shared__ int  regid[64];

    int tid = threadIdx.x, wid = tid >> 5, lane = tid & 31;
    int g = lane >> 2, ct = lane & 3;

    // ---- load q/k head slice + transposed v ----
    #pragma unroll
    for (int i = 0; i < 2; i++) {
        int idx = tid + i*128;           // 0..255 over (t, chunk of 8 halves)
        int t = idx >> 2, ch = idx & 3;
        size_t base = (size_t)(widx*64 + t) * (3*DIMC) + head*32 + ch*8;
        uint4 qv = *(const uint4*)(qkv + base);
        uint4 kv = *(const uint4*)(qkv + base + DIMC);
        uint4 vv = *(const uint4*)(qkv + base + 2*DIMC);
        *(uint4*)(qs  + t*40 + ch*8) = qv;
        *(uint4*)(ksm + t*40 + ch*8) = kv;
        const bf16* vp = (const bf16*)&vv;
        #pragma unroll
        for (int j = 0; j < 8; j++) vt[(ch*8 + j)*72 + t] = vp[j];
    }
    if (tid < 64) {
        int iy = tid >> 3, ix = tid & 7;
        int rh = (wy < 7) ? 0 : ((iy < SSZ) ? 1 : 2);
        int rw = (wx < 7) ? 0 : ((ix < SSZ) ? 1 : 2);
        regid[tid] = rh*3 + rw;
    }
    __syncthreads();

    int a_roff = (lane & 15);
    int a_koff = (lane >> 4) * 8;
    int b_roff = ((lane >> 4) & 1) * 8 + (lane & 7);
    int b_koff = ((lane >> 3) & 1) * 8;

    // ---- S = Q @ K^T : warp rows wid*16..+15, all 64 cols ----
    uint32_t qa[2][4];
    #pragma unroll
    for (int ks = 0; ks < 2; ks++)
        ldmat_x4(qa[ks], smem_u32(qs + (wid*16 + a_roff)*40 + ks*16 + a_koff));

    float S[8][4];
    #pragma unroll
    for (int tn = 0; tn < 8; tn++)
        #pragma unroll
        for (int e = 0; e < 4; e++) S[tn][e] = 0.f;

    #pragma unroll
    for (int tnp = 0; tnp < 4; tnp++) {
        #pragma unroll
        for (int ks = 0; ks < 2; ks++) {
            uint32_t kb[4];
            ldmat_x4(kb, smem_u32(ksm + (tnp*16 + b_roff)*40 + ks*16 + b_koff));
            mma_bf16(S[2*tnp],   qa[ks][0], qa[ks][1], qa[ks][2], qa[ks][3], kb[0], kb[1]);
            mma_bf16(S[2*tnp+1], qa[ks][0], qa[ks][1], qa[ks][2], qa[ks][3], kb[2], kb[3]);
        }
    }

    // ---- scale + relative-position bias + mask, register softmax ----
    int r0 = wid*16 + g, r1 = r0 + 8;
    int reg0 = regid[r0], reg1 = regid[r1];
    float mx0 = -1e30f, mx1 = -1e30f;
    #pragma unroll
    for (int tn = 0; tn < 8; tn++) {
        #pragma unroll
        for (int e = 0; e < 4; e++) {
            int p  = (e < 2) ? r0 : r1;
            int qq = tn*8 + ct*2 + (e & 1);
            int dx = (p & 7) - (qq & 7);
            int dy = (p >> 3) - (qq >> 3);
            float bias = __ldg(&rpb[((dx + 7)*15 + (dy + 7))*HEADS + head]);
            float v = S[tn][e]*QSCALE + bias;
            if (((e < 2) ? reg0 : reg1) == regid[qq]) v -= 100.f;
            S[tn][e] = v;
            if (e < 2) mx0 = fmaxf(mx0, v); else mx1 = fmaxf(mx1, v);
        }
    }
    #pragma unroll
    for (int off = 1; off <= 2; off <<= 1) {
        mx0 = fmaxf(mx0, __shfl_xor_sync(0xffffffffu, mx0, off));
        mx1 = fmaxf(mx1, __shfl_xor_sync(0xffffffffu, mx1, off));
    }
    float sm0 = 0.f, sm1 = 0.f;
    #pragma unroll
    for (int tn = 0; tn < 8; tn++) {
        S[tn][0] = __expf(S[tn][0] - mx0); sm0 += S[tn][0];
        S[tn][1] = __expf(S[tn][1] - mx0); sm0 += S[tn][1];
        S[tn][2] = __expf(S[tn][2] - mx1); sm1 += S[tn][2];
        S[tn][3] = __expf(S[tn][3] - mx1); sm1 += S[tn][3];
    }
    #pragma unroll
    for (int off = 1; off <= 2; off <<= 1) {
        sm0 += __shfl_xor_sync(0xffffffffu, sm0, off);
        sm1 += __shfl_xor_sync(0xffffffffu, sm1, off);
    }
    float inv0 = 1.f / sm0, inv1 = 1.f / sm1;

    // ---- O = P @ V (P unnormalized bf16; normalize at the end) ----
    float O[4][4];
    #pragma unroll
    for (int dn = 0; dn < 4; dn++)
        #pragma unroll
        for (int e = 0; e < 4; e++) O[dn][e] = 0.f;

    #pragma unroll
    for (int kt = 0; kt < 4; kt++) {
        uint32_t pa0 = pack_bf16x2(S[2*kt][0],   S[2*kt][1]);
        uint32_t pa1 = pack_bf16x2(S[2*kt][2],   S[2*kt][3]);
        uint32_t pa2 = pack_bf16x2(S[2*kt+1][0], S[2*kt+1][1]);
        uint32_t pa3 = pack_bf16x2(S[2*kt+1][2], S[2*kt+1][3]);
        #pragma unroll
        for (int dnp = 0; dnp < 2; dnp++) {
            uint32_t vb[4];
            ldmat_x4(vb, smem_u32(vt + (dnp*16 + b_roff)*72 + kt*16 + b_koff));
            mma_bf16(O[2*dnp],   pa0, pa1, pa2, pa3, vb[0], vb[1]);
            mma_bf16(O[2*dnp+1], pa0, pa1, pa2, pa3, vb[2], vb[3]);
        }
    }

    // ---- write out (bf16), normalized ----
    size_t row0 = (size_t)(widx*64 + r0);
    size_t row1 = (size_t)(widx*64 + r1);
    #pragma unroll
    for (int dn = 0; dn < 4; dn++) {
        int col = head*32 + dn*8 + ct*2;
        *(__nv_bfloat162*)(out + row0*DIMC + col) =
            __floats2bfloat162_rn(O[dn][0]*inv0, O[dn][1]*inv0);
        *(__nv_bfloat162*)(out + row1*DIMC + col) =
            __floats2bfloat162_rn(O[dn][2]*inv1, O[dn][3]*inv1);
    }
}

// ---------------------------------- launch --------------------------------------
extern "C" void kernel_launch(void* const* d_in, const int* in_sizes, int n_in,
                              void* d_out, int out_size)
{
    const float* x      = (const float*)d_in[0];
    const float* n1g    = (const float*)d_in[1];
    const float* n1b    = (const float*)d_in[2];
    const float* qkv_w  = (const float*)d_in[3];
    const float* qkv_b  = (const float*)d_in[4];
    const float* rpb    = (const float*)d_in[5];
    const float* proj_w = (const float*)d_in[6];
    const float* proj_b = (const float*)d_in[7];
    const float* n2g    = (const float*)d_in[8];
    const float* n2b    = (const float*)d_in[9];
    const float* fc1_w  = (const float*)d_in[10];
    const float* fc1_b  = (const float*)d_in[11];
    const float* fc2_w  = (const float*)d_in[12];
    const float* fc2_b  = (const float*)d_in[13];
    float* out = (float*)d_out;

    bf16 *xw, *qkvbuf, *attn, *yn, *m1;
    float *y;
    bf16 *wt_qkv, *wt_proj, *wt_fc1, *wt_fc2;
    cudaGetSymbolAddress((void**)&xw,      g_xw);
    cudaGetSymbolAddress((void**)&qkvbuf,  g_qkv);
    cudaGetSymbolAddress((void**)&attn,    g_attn);
    cudaGetSymbolAddress((void**)&y,       g_y);
    cudaGetSymbolAddress((void**)&yn,      g_yn);
    cudaGetSymbolAddress((void**)&m1,      g_m1);
    cudaGetSymbolAddress((void**)&wt_qkv,  g_wt_qkv);
    cudaGetSymbolAddress((void**)&wt_proj, g_wt_proj);
    cudaGetSymbolAddress((void**)&wt_fc1,  g_wt_fc1);
    cudaGetSymbolAddress((void**)&wt_fc2,  g_wt_fc2);

    const int SMEM = 8 * ASTG;   // 81920 B
    cudaFuncSetAttribute((mma_gemm<0, bf16>),  cudaFuncAttributeMaxDynamicSharedMemorySize, SMEM);
    cudaFuncSetAttribute((mma_gemm<1, bf16>),  cudaFuncAttributeMaxDynamicSharedMemorySize, SMEM);
    cudaFuncSetAttribute((mma_gemm<2, float>), cudaFuncAttributeMaxDynamicSharedMemorySize, SMEM);
    cudaFuncSetAttribute((mma_gemm<3, float>), cudaFuncAttributeMaxDynamicSharedMemorySize, SMEM);

    dim3 t32(32, 8);
    // weight transposes (cheap; weights L2-resident afterwards)
    transpose_kernel<<<dim3(768/32, 256/32),  t32>>>(qkv_w,  wt_qkv,  256, 768);
    transpose_kernel<<<dim3(256/32, 256/32),  t32>>>(proj_w, wt_proj, 256, 256);
    transpose_kernel<<<dim3(1024/32, 256/32), t32>>>(fc1_w,  wt_fc1,  256, 1024);
    transpose_kernel<<<dim3(256/32, 1024/32), t32>>>(fc2_w,  wt_fc2,  1024, 256);

    // 1) LN1 + cyclic shift + window partition (bf16 out)
    ln_kernel<<<ROWS/8, 256>>>(x, n1g, n1b, xw, 1);
    // 2) QKV GEMM: [65536,256] @ [256,768] -> bf16
    mma_gemm<0, bf16><<<dim3(768/128, ROWS/128), 256, SMEM>>>(xw, wt_qkv, qkv_b, nullptr,
                                                              qkvbuf, ROWS, 768, 256);
    // 3) windowed attention (tensor cores) -> bf16
    attn_kernel<<<ROWS/64*HEADS, 128>>>(qkvbuf, rpb, attn);
    // 4) proj GEMM + window-reverse/shift scatter + residual(x) -> y (fp32)
    mma_gemm<2, float><<<dim3(256/128, ROWS/128), 256, SMEM>>>(attn, wt_proj, proj_b, x,
                                                               y, ROWS, 256, 256);
    // 5) LN2 (bf16 out)
    ln_kernel<<<ROWS/8, 256>>>(y, n2g, n2b, yn, 0);
    // 6) fc1 + exact GELU -> bf16
    mma_gemm<1, bf16><<<dim3(1024/128, ROWS/128), 256, SMEM>>>(yn, wt_fc1, fc1_b, nullptr,
                                                               m1, ROWS, 1024, 256);
    // 7) fc2 + residual with ORIGINAL shortcut x -> out (fp32)
    mma_gemm<3, float><<<dim3(256/128, ROWS/128), 256, SMEM>>>(m1, wt_fc2, fc2_b, x,
                                                               out, ROWS, 256, 1024);
}

// round 6
// speedup vs baseline: 4.6352x; 1.0216x over previous
#include <cuda_runtime.h>
#include <cuda_bf16.h>
#include <math.h>
#include <cstdint>

#define DIMC 256
#define HEADS 8
#define WSZ 8
#define SSZ 4
#define BATCH 16
#define IMG 64
#define ROWS (BATCH*IMG*IMG)   /* 65536 token rows */
#define QSCALE 0.17677669529663687f

typedef __nv_bfloat16 bf16;

// ---------------- scratch (device globals; no allocation allowed) ----------------
__device__ __align__(16) bf16  g_xw  [ROWS*DIMC];      // LN1 + shift + window partition
__device__ __align__(16) bf16  g_qkv [ROWS*3*DIMC];    // qkv projections
__device__ __align__(16) bf16  g_attn[ROWS*DIMC];      // attention output (window layout)
__device__ __align__(16) bf16  g_yn  [ROWS*DIMC];      // LN2(x + proj)
__device__ __align__(16) bf16  g_m1  [ROWS*4*DIMC];    // gelu(fc1)
// transposed weights  WT[n*K + k] = W[k*N + n]   (bf16)
__device__ __align__(16) bf16 g_wt_qkv [768*256];
__device__ __align__(16) bf16 g_wt_proj[256*256];
__device__ __align__(16) bf16 g_wt_fc1 [1024*256];
__device__ __align__(16) bf16 g_wt_fc2 [256*1024];

// ---------------- helpers --------------------------------------------------------
__device__ __forceinline__ uint32_t smem_u32(const void* p) {
    uint32_t a;
    asm("{ .reg .u64 t; cvta.to.shared.u64 t, %1; cvt.u32.u64 %0, t; }" : "=r"(a) : "l"(p));
    return a;
}
#define CP_ASYNC16(dst, src) \
    asm volatile("cp.async.cg.shared.global [%0], [%1], 16;" :: "r"(dst), "l"(src))
#define CP_COMMIT() asm volatile("cp.async.commit_group;")
#define CP_WAIT2()  asm volatile("cp.async.wait_group 2;")
#define CP_WAIT1()  asm volatile("cp.async.wait_group 1;")
#define CP_WAIT0()  asm volatile("cp.async.wait_group 0;")

__device__ __forceinline__ void mma_bf16(float c[4], uint32_t a0, uint32_t a1,
                                         uint32_t a2, uint32_t a3,
                                         uint32_t b0, uint32_t b1) {
    asm volatile(
        "mma.sync.aligned.m16n8k16.row.col.f32.bf16.bf16.f32 "
        "{%0,%1,%2,%3}, {%4,%5,%6,%7}, {%8,%9}, {%0,%1,%2,%3};"
        : "+f"(c[0]), "+f"(c[1]), "+f"(c[2]), "+f"(c[3])
        : "r"(a0), "r"(a1), "r"(a2), "r"(a3), "r"(b0), "r"(b1));
}
__device__ __forceinline__ void ldmat_x4(uint32_t r[4], uint32_t saddr) {
    asm volatile("ldmatrix.sync.aligned.m8n8.x4.shared.b16 {%0,%1,%2,%3}, [%4];"
                 : "=r"(r[0]), "=r"(r[1]), "=r"(r[2]), "=r"(r[3]) : "r"(saddr));
}
__device__ __forceinline__ uint32_t pack_bf16x2(float lo, float hi) {
    __nv_bfloat162 h = __floats2bfloat162_rn(lo, hi);
    return *(uint32_t*)&h;
}

// ---------------- LayerNorm: one warp per row, float4 loads, bf16 out -----------
__global__ void ln_kernel(const float* __restrict__ in, const float* __restrict__ g,
                          const float* __restrict__ b, bf16* __restrict__ out,
                          int shiftmode)
{
    int o = (blockIdx.x * blockDim.x + threadIdx.x) >> 5;   // row
    int lane = threadIdx.x & 31;
    int src = o;
    if (shiftmode) {
        int widx = o >> 6, n = o & 63;
        int bb = widx >> 6, wi = widx & 63;
        int wy = wi >> 3, wx = wi & 7;
        int iy = n >> 3,  ix = n & 7;
        int sh = (wy*8 + iy + SSZ) & 63;
        int sw = (wx*8 + ix + SSZ) & 63;
        src = bb*4096 + sh*64 + sw;
    }
    const float4* p = (const float4*)(in + (size_t)src*DIMC + lane*8);
    float4 v0 = p[0], v1 = p[1];
    float s  = v0.x+v0.y+v0.z+v0.w + v1.x+v1.y+v1.z+v1.w;
    float s2 = v0.x*v0.x+v0.y*v0.y+v0.z*v0.z+v0.w*v0.w
             + v1.x*v1.x+v1.y*v1.y+v1.z*v1.z+v1.w*v1.w;
    #pragma unroll
    for (int off = 16; off; off >>= 1) {
        s  += __shfl_xor_sync(0xffffffffu, s,  off);
        s2 += __shfl_xor_sync(0xffffffffu, s2, off);
    }
    float mean = s * (1.f/DIMC);
    float var  = s2 * (1.f/DIMC) - mean*mean;
    float r = rsqrtf(var + 1e-5f);
    const float4* gp = (const float4*)(g + lane*8);
    const float4* bp = (const float4*)(b + lane*8);
    float4 g0 = gp[0], g1 = gp[1], b0 = bp[0], b1 = bp[1];
    union { uint4 u; bf16 h[8]; } res;
    res.h[0] = __float2bfloat16((v0.x-mean)*r*g0.x + b0.x);
    res.h[1] = __float2bfloat16((v0.y-mean)*r*g0.y + b0.y);
    res.h[2] = __float2bfloat16((v0.z-mean)*r*g0.z + b0.z);
    res.h[3] = __float2bfloat16((v0.w-mean)*r*g0.w + b0.w);
    res.h[4] = __float2bfloat16((v1.x-mean)*r*g1.x + b1.x);
    res.h[5] = __float2bfloat16((v1.y-mean)*r*g1.y + b1.y);
    res.h[6] = __float2bfloat16((v1.z-mean)*r*g1.z + b1.z);
    res.h[7] = __float2bfloat16((v1.w-mean)*r*g1.w + b1.w);
    *(uint4*)(out + (size_t)o*DIMC + lane*8) = res.u;
}

// ---------------- weight transpose (+ bf16 round): WT[n*K+k] = W[k*N+n] --------
__global__ void transpose_kernel(const float* __restrict__ w, bf16* __restrict__ wt,
                                 int K, int N)
{
    __shared__ float t[32][33];
    int k0 = blockIdx.y*32, n0 = blockIdx.x*32;
    int tx = threadIdx.x, ty = threadIdx.y;   // 32 x 8
    #pragma unroll
    for (int i = ty; i < 32; i += 8) t[i][tx] = w[(size_t)(k0+i)*N + n0 + tx];
    __syncthreads();
    #pragma unroll
    for (int i = ty; i < 32; i += 8)
        wt[(size_t)(n0+i)*K + k0 + tx] = __float2bfloat16(t[tx][i]);
}

// ============ bf16 mma.sync GEMM: 128x128x32 tiles, 4-stage cp.async ============
// D[M,N] = A[M,K] @ B[K,N]  (B supplied transposed: BT[N,K]); bf16 in, fp32 accum.
// MODE 0: bf16(+bias)    MODE 1: bf16(gelu(+bias))    MODE 3: f32: res+bias
#define PADH 40                      /* halves per 32-half row in smem */
#define ASTG (128*PADH*2)            /* bytes per stage per operand = 10240 */
template<int MODE, typename OutT>
__global__ __launch_bounds__(256, 2)
void mma_gemm(const bf16* __restrict__ A, const bf16* __restrict__ BT,
              const float* __restrict__ bias, const float* __restrict__ res,
              OutT* __restrict__ C, int M, int N, int K)
{
    extern __shared__ char smem[];   // A stages [0..3] | B stages [0..3]
    int tid = threadIdx.x, wid = tid >> 5, lane = tid & 31;
    int g = lane >> 2, ct = lane & 3;
    int wm = wid & 1, wn = wid >> 1;          // 2 x 4 warp grid
    int bm = blockIdx.y * 128, bn = blockIdx.x * 128;
    const bf16* Ab = A  + (size_t)bm * K;
    const bf16* Bb = BT + (size_t)bn * K;
    const int T = K / 32;

    int f_row = tid >> 1;
    int f_cb  = (tid & 1) * 2;

    #define FILL(t, s) do { \
        char* as_ = smem + (s)*ASTG; \
        char* bs_ = smem + 4*ASTG + (s)*ASTG; \
        _Pragma("unroll") \
        for (int i = 0; i < 2; i++) { \
            int c = f_cb + i; \
            CP_ASYNC16(smem_u32(as_ + f_row*(PADH*2) + c*16), \
                       Ab + (size_t)f_row*K + (t)*32 + c*8); \
            CP_ASYNC16(smem_u32(bs_ + f_row*(PADH*2) + c*16), \
                       Bb + (size_t)f_row*K + (t)*32 + c*8); \
        } \
        CP_COMMIT(); \
    } while (0)

    float acc[4][4][4];
    #pragma unroll
    for (int i = 0; i < 4; i++)
        #pragma unroll
        for (int j = 0; j < 4; j++)
            #pragma unroll
            for (int e = 0; e < 4; e++) acc[i][j][e] = 0.f;

    FILL(0, 0); FILL(1, 1); FILL(2, 2);

    int a_roff = (lane & 15);
    int a_koff = (lane >> 4) * 8;
    int b_roff = ((lane >> 4) & 1) * 8 + (lane & 7);
    int b_koff = ((lane >> 3) & 1) * 8;

    for (int t = 0; t < T; t++) {
        int rem = T - 1 - t;
        if (rem >= 2) CP_WAIT2(); else if (rem == 1) CP_WAIT1(); else CP_WAIT0();
        __syncthreads();                 // single barrier per K-tile
        if (t + 3 < T) FILL(t + 3, (t + 3) & 3);

        int s = t & 3;
        const bf16* Ap = (const bf16*)(smem + s*ASTG);
        const bf16* Bp = (const bf16*)(smem + 4*ASTG + s*ASTG);
        #pragma unroll
        for (int ks = 0; ks < 2; ks++) {
            int k = ks*16;
            uint32_t af[4][4], bfr[2][4];
            #pragma unroll
            for (int tm = 0; tm < 4; tm++)
                ldmat_x4(af[tm], smem_u32(Ap + (wm*64 + tm*16 + a_roff)*PADH + k + a_koff));
            #pragma unroll
            for (int tnp = 0; tnp < 2; tnp++)
                ldmat_x4(bfr[tnp], smem_u32(Bp + (wn*32 + tnp*16 + b_roff)*PADH + k + b_koff));
            #pragma unroll
            for (int tm = 0; tm < 4; tm++)
                #pragma unroll
                for (int tnp = 0; tnp < 2; tnp++) {
                    mma_bf16(acc[tm][2*tnp],   af[tm][0], af[tm][1], af[tm][2], af[tm][3],
                             bfr[tnp][0], bfr[tnp][1]);
                    mma_bf16(acc[tm][2*tnp+1], af[tm][0], af[tm][1], af[tm][2], af[tm][3],
                             bfr[tnp][2], bfr[tnp][3]);
                }
        }
    }
    #undef FILL

    // ---- epilogue ----
    #pragma unroll
    for (int tm = 0; tm < 4; tm++) {
        int r0 = bm + wm*64 + tm*16 + g;
        #pragma unroll
        for (int half = 0; half < 2; half++) {
            int r = r0 + half*8;
            size_t dst = r;
            #pragma unroll
            for (int tn = 0; tn < 4; tn++) {
                int col = bn + wn*32 + tn*8 + ct*2;
                float v0 = acc[tm][tn][half*2]     + bias[col];
                float v1 = acc[tm][tn][half*2 + 1] + bias[col + 1];
                if (MODE == 1) {
                    v0 = 0.5f * v0 * (1.f + erff(v0 * 0.7071067811865475f));
                    v1 = 0.5f * v1 * (1.f + erff(v1 * 0.7071067811865475f));
                }
                if (MODE == 3) {
                    const float2 rr = *(const float2*)(res + dst*(size_t)N + col);
                    v0 += rr.x; v1 += rr.y;
                    *(float2*)((float*)C + dst*(size_t)N + col) = make_float2(v0, v1);
                } else {
                    __nv_bfloat162 h = __floats2bfloat162_rn(v0, v1);
                    *(__nv_bfloat162*)((bf16*)C + dst*(size_t)N + col) = h;
                }
            }
        }
    }
}

// ====== fused proj GEMM + window-reverse/shift scatter + residual + LN2 =========
// Tile 128 x 256 (full row). yn[dst] = LN(x[dst] + attn@Wp + bias), bf16 out.
#define PSTG_A (128*PADH*2)          /* 10240 B */
#define PSTG_B (256*PADH*2)          /* 20480 B */
#define PSTG   (PSTG_A + PSTG_B)
__global__ __launch_bounds__(256, 1)
void proj_ln_kernel(const bf16* __restrict__ A, const bf16* __restrict__ BT,
                    const float* __restrict__ bias, const float* __restrict__ x,
                    const float* __restrict__ g2, const float* __restrict__ b2,
                    bf16* __restrict__ yn)
{
    extern __shared__ char smem[];   // 3 stages of (A | B)
    const int K = 256, T = 8;
    int tid = threadIdx.x, wid = tid >> 5, lane = tid & 31;
    int g = lane >> 2, ct = lane & 3;
    int wm = wid & 1, wn = wid >> 1;          // 2 x 4: 64 rows x 64 cols per warp
    int bm = blockIdx.x * 128;
    const bf16* Ab = A + (size_t)bm * K;

    int f_row = tid >> 1;
    int f_cb  = (tid & 1) * 2;

    #define PFILL(t, s) do { \
        char* as_ = smem + (s)*PSTG; \
        char* bs_ = as_ + PSTG_A; \
        _Pragma("unroll") \
        for (int i = 0; i < 2; i++) { \
            int c = f_cb + i; \
            CP_ASYNC16(smem_u32(as_ + f_row*(PADH*2) + c*16), \
                       Ab + (size_t)f_row*K + (t)*32 + c*8); \
            CP_ASYNC16(smem_u32(bs_ + f_row*(PADH*2) + c*16), \
                       BT + (size_t)f_row*K + (t)*32 + c*8); \
            CP_ASYNC16(smem_u32(bs_ + (f_row+128)*(PADH*2) + c*16), \
                       BT + (size_t)(f_row+128)*K + (t)*32 + c*8); \
        } \
        CP_COMMIT(); \
    } while (0)

    float acc[4][8][4];
    #pragma unroll
    for (int i = 0; i < 4; i++)
        #pragma unroll
        for (int j = 0; j < 8; j++)
            #pragma unroll
            for (int e = 0; e < 4; e++) acc[i][j][e] = 0.f;

    PFILL(0, 0); PFILL(1, 1);

    int a_roff = (lane & 15);
    int a_koff = (lane >> 4) * 8;
    int b_roff = ((lane >> 4) & 1) * 8 + (lane & 7);
    int b_koff = ((lane >> 3) & 1) * 8;

    for (int t = 0; t < T; t++) {
        int rem = T - 1 - t;
        if (rem >= 1) CP_WAIT1(); else CP_WAIT0();
        __syncthreads();
        if (t + 2 < T) PFILL(t + 2, (t + 2) % 3);

        int s = t % 3;
        const bf16* Ap = (const bf16*)(smem + s*PSTG);
        const bf16* Bp = (const bf16*)(smem + s*PSTG + PSTG_A);
        #pragma unroll
        for (int ks = 0; ks < 2; ks++) {
            int k = ks*16;
            uint32_t af[4][4];
            #pragma unroll
            for (int tm = 0; tm < 4; tm++)
                ldmat_x4(af[tm], smem_u32(Ap + (wm*64 + tm*16 + a_roff)*PADH + k + a_koff));
            #pragma unroll
            for (int tnp = 0; tnp < 4; tnp++) {
                uint32_t bfr[4];
                ldmat_x4(bfr, smem_u32(Bp + (wn*64 + tnp*16 + b_roff)*PADH + k + b_koff));
                #pragma unroll
                for (int tm = 0; tm < 4; tm++) {
                    mma_bf16(acc[tm][2*tnp],   af[tm][0], af[tm][1], af[tm][2], af[tm][3],
                             bfr[0], bfr[1]);
                    mma_bf16(acc[tm][2*tnp+1], af[tm][0], af[tm][1], af[tm][2], af[tm][3],
                             bfr[2], bfr[3]);
                }
            }
        }
    }
    #undef PFILL

    // ---- epilogue: v = acc + bias + x[dst]; row LN; yn[dst] = LN(v) -------------
    float s1[8], s2a[8];
    size_t dsts[8];
    // per-thread column constants
    float2 bi[8];
    #pragma unroll
    for (int tn = 0; tn < 8; tn++)
        bi[tn] = *(const float2*)(bias + wn*64 + tn*8 + ct*2);

    #pragma unroll
    for (int tm = 0; tm < 4; tm++) {
        #pragma unroll
        for (int half = 0; half < 2; half++) {
            int rr = tm*2 + half;
            int r = bm + wm*64 + tm*16 + g + half*8;
            // window-reverse + shift scatter
            int widx = r >> 6, n = r & 63;
            int bb2 = widx >> 6, wi = widx & 63;
            int wy = wi >> 3, wx = wi & 7;
            int iy = n >> 3,  ix = n & 7;
            int dh = (wy*8 + iy + SSZ) & 63;
            int dw = (wx*8 + ix + SSZ) & 63;
            size_t dst = (size_t)(bb2*4096 + dh*64 + dw);
            dsts[rr] = dst;
            float s = 0.f, ss = 0.f;
            #pragma unroll
            for (int tn = 0; tn < 8; tn++) {
                int col = wn*64 + tn*8 + ct*2;
                float2 xr = *(const float2*)(x + dst*(size_t)DIMC + col);
                float v0 = acc[tm][tn][half*2]     + bi[tn].x + xr.x;
                float v1 = acc[tm][tn][half*2 + 1] + bi[tn].y + xr.y;
                acc[tm][tn][half*2] = v0; acc[tm][tn][half*2+1] = v1;
                s += v0 + v1; ss += v0*v0 + v1*v1;
            }
            s1[rr] = s; s2a[rr] = ss;
        }
    }
    #pragma unroll
    for (int rr = 0; rr < 8; rr++) {
        #pragma unroll
        for (int off = 1; off <= 2; off <<= 1) {
            s1[rr]  += __shfl_xor_sync(0xffffffffu, s1[rr],  off);
            s2a[rr] += __shfl_xor_sync(0xffffffffu, s2a[rr], off);
        }
    }
    __syncthreads();                              // stages dead; reuse smem
    float* part = (float*)smem;                   // [128][4][2]
    if (ct == 0) {
        #pragma unroll
        for (int rr = 0; rr < 8; rr++) {
            int tm = rr >> 1, half = rr & 1;
            int rl = wm*64 + tm*16 + g + half*8;
            part[(rl*4 + wn)*2]     = s1[rr];
            part[(rl*4 + wn)*2 + 1] = s2a[rr];
        }
    }
    __syncthreads();

    float2 gg[8], bb[8];
    #pragma unroll
    for (int tn = 0; tn < 8; tn++) {
        int col = wn*64 + tn*8 + ct*2;
        gg[tn] = *(const float2*)(g2 + col);
        bb[tn] = *(const float2*)(b2 + col);
    }
    #pragma unroll
    for (int tm = 0; tm < 4; tm++) {
        #pragma unroll
        for (int half = 0; half < 2; half++) {
            int rr = tm*2 + half;
            int rl = wm*64 + tm*16 + g + half*8;
            float s = 0.f, ss = 0.f;
            #pragma unroll
            for (int w = 0; w < 4; w++) {
                s  += part[(rl*4 + w)*2];
                ss += part[(rl*4 + w)*2 + 1];
            }
            float mean = s * (1.f/DIMC);
            float var  = ss * (1.f/DIMC) - mean*mean;
            float rinv = rsqrtf(var + 1e-5f);
            size_t dst = dsts[rr];
            #pragma unroll
            for (int tn = 0; tn < 8; tn++) {
                int col = wn*64 + tn*8 + ct*2;
                float v0 = (acc[tm][tn][half*2]     - mean)*rinv*gg[tn].x + bb[tn].x;
                float v1 = (acc[tm][tn][half*2 + 1] - mean)*rinv*gg[tn].y + bb[tn].y;
                *(__nv_bfloat162*)(yn + dst*(size_t)DIMC + col) =
                    __floats2bfloat162_rn(v0, v1);
            }
        }
    }
}

// ======== tensor-core windowed attention: block = (window, head), 4 warps =======
__global__ __launch_bounds__(128)
void attn_kernel(const bf16* __restrict__ qkv, const float* __restrict__ rpb,
                 bf16* __restrict__ out)
{
    int bid  = blockIdx.x;      // widx*8 + head
    int head = bid & 7;
    int widx = bid >> 3;
    int wi = widx & 63;
    int wy = wi >> 3, wx = wi & 7;

    __shared__ bf16 qs[64*40];      // [token][d pad 40]
    __shared__ bf16 ksm[64*40];
    __shared__ bf16 vt[32*72];      // [d][token pad 72]
    __shared__ int  regid[64];

    int tid = threadIdx.x, wid = tid >> 5, lane = tid & 31;
    int g = lane >> 2, ct = lane & 3;

    #pragma unroll
    for (int i = 0; i < 2; i++) {
        int idx = tid + i*128;
        int t = idx >> 2, ch = idx & 3;
        size_t base = (size_t)(widx*64 + t) * (3*DIMC) + head*32 + ch*8;
        uint4 qv = *(const uint4*)(qkv + base);
        uint4 kv = *(const uint4*)(qkv + base + DIMC);
        uint4 vv = *(const uint4*)(qkv + base + 2*DIMC);
        *(uint4*)(qs  + t*40 + ch*8) = qv;
        *(uint4*)(ksm + t*40 + ch*8) = kv;
        const bf16* vp = (const bf16*)&vv;
        #pragma unroll
        for (int j = 0; j < 8; j++) vt[(ch*8 + j)*72 + t] = vp[j];
    }
    if (tid < 64) {
        int iy = tid >> 3, ix = tid & 7;
        int rh = (wy < 7) ? 0 : ((iy < SSZ) ? 1 : 2);
        int rw = (wx < 7) ? 0 : ((ix < SSZ) ? 1 : 2);
        regid[tid] = rh*3 + rw;
    }
    __syncthreads();

    int a_roff = (lane & 15);
    int a_koff = (lane >> 4) * 8;
    int b_roff = ((lane >> 4) & 1) * 8 + (lane & 7);
    int b_koff = ((lane >> 3) & 1) * 8;

    uint32_t qa[2][4];
    #pragma unroll
    for (int ks = 0; ks < 2; ks++)
        ldmat_x4(qa[ks], smem_u32(qs + (wid*16 + a_roff)*40 + ks*16 + a_koff));

    float S[8][4];
    #pragma unroll
    for (int tn = 0; tn < 8; tn++)
        #pragma unroll
        for (int e = 0; e < 4; e++) S[tn][e] = 0.f;

    #pragma unroll
    for (int tnp = 0; tnp < 4; tnp++) {
        #pragma unroll
        for (int ks = 0; ks < 2; ks++) {
            uint32_t kb[4];
            ldmat_x4(kb, smem_u32(ksm + (tnp*16 + b_roff)*40 + ks*16 + b_koff));
            mma_bf16(S[2*tnp],   qa[ks][0], qa[ks][1], qa[ks][2], qa[ks][3], kb[0], kb[1]);
            mma_bf16(S[2*tnp+1], qa[ks][0], qa[ks][1], qa[ks][2], qa[ks][3], kb[2], kb[3]);
        }
    }

    int r0 = wid*16 + g, r1 = r0 + 8;
    int reg0 = regid[r0], reg1 = regid[r1];
    float mx0 = -1e30f, mx1 = -1e30f;
    #pragma unroll
    for (int tn = 0; tn < 8; tn++) {
        #pragma unroll
        for (int e = 0; e < 4; e++) {
            int p  = (e < 2) ? r0 : r1;
            int qq = tn*8 + ct*2 + (e & 1);
            int dx = (p & 7) - (qq & 7);
            int dy = (p >> 3) - (qq >> 3);
            float bias = __ldg(&rpb[((dx + 7)*15 + (dy + 7))*HEADS + head]);
            float v = S[tn][e]*QSCALE + bias;
            if (((e < 2) ? reg0 : reg1) == regid[qq]) v -= 100.f;
            S[tn][e] = v;
            if (e < 2) mx0 = fmaxf(mx0, v); else mx1 = fmaxf(mx1, v);
        }
    }
    #pragma unroll
    for (int off = 1; off <= 2; off <<= 1) {
        mx0 = fmaxf(mx0, __shfl_xor_sync(0xffffffffu, mx0, off));
        mx1 = fmaxf(mx1, __shfl_xor_sync(0xffffffffu, mx1, off));
    }
    float sm0 = 0.f, sm1 = 0.f;
    #pragma unroll
    for (int tn = 0; tn < 8; tn++) {
        S[tn][0] = __expf(S[tn][0] - mx0); sm0 += S[tn][0];
        S[tn][1] = __expf(S[tn][1] - mx0); sm0 += S[tn][1];
        S[tn][2] = __expf(S[tn][2] - mx1); sm1 += S[tn][2];
        S[tn][3] = __expf(S[tn][3] - mx1); sm1 += S[tn][3];
    }
    #pragma unroll
    for (int off = 1; off <= 2; off <<= 1) {
        sm0 += __shfl_xor_sync(0xffffffffu, sm0, off);
        sm1 += __shfl_xor_sync(0xffffffffu, sm1, off);
    }
    float inv0 = 1.f / sm0, inv1 = 1.f / sm1;

    float O[4][4];
    #pragma unroll
    for (int dn = 0; dn < 4; dn++)
        #pragma unroll
        for (int e = 0; e < 4; e++) O[dn][e] = 0.f;

    #pragma unroll
    for (int kt = 0; kt < 4; kt++) {
        uint32_t pa0 = pack_bf16x2(S[2*kt][0],   S[2*kt][1]);
        uint32_t pa1 = pack_bf16x2(S[2*kt][2],   S[2*kt][3]);
        uint32_t pa2 = pack_bf16x2(S[2*kt+1][0], S[2*kt+1][1]);
        uint32_t pa3 = pack_bf16x2(S[2*kt+1][2], S[2*kt+1][3]);
        #pragma unroll
        for (int dnp = 0; dnp < 2; dnp++) {
            uint32_t vb[4];
            ldmat_x4(vb, smem_u32(vt + (dnp*16 + b_roff)*72 + kt*16 + b_koff));
            mma_bf16(O[2*dnp],   pa0, pa1, pa2, pa3, vb[0], vb[1]);
            mma_bf16(O[2*dnp+1], pa0, pa1, pa2, pa3, vb[2], vb[3]);
        }
    }

    size_t row0 = (size_t)(widx*64 + r0);
    size_t row1 = (size_t)(widx*64 + r1);
    #pragma unroll
    for (int dn = 0; dn < 4; dn++) {
        int col = head*32 + dn*8 + ct*2;
        *(__nv_bfloat162*)(out + row0*DIMC + col) =
            __floats2bfloat162_rn(O[dn][0]*inv0, O[dn][1]*inv0);
        *(__nv_bfloat162*)(out + row1*DIMC + col) =
            __floats2bfloat162_rn(O[dn][2]*inv1, O[dn][3]*inv1);
    }
}

// ---------------------------------- launch --------------------------------------
extern "C" void kernel_launch(void* const* d_in, const int* in_sizes, int n_in,
                              void* d_out, int out_size)
{
    const float* x      = (const float*)d_in[0];
    const float* n1g    = (const float*)d_in[1];
    const float* n1b    = (const float*)d_in[2];
    const float* qkv_w  = (const float*)d_in[3];
    const float* qkv_b  = (const float*)d_in[4];
    const float* rpb    = (const float*)d_in[5];
    const float* proj_w = (const float*)d_in[6];
    const float* proj_b = (const float*)d_in[7];
    const float* n2g    = (const float*)d_in[8];
    const float* n2b    = (const float*)d_in[9];
    const float* fc1_w  = (const float*)d_in[10];
    const float* fc1_b  = (const float*)d_in[11];
    const float* fc2_w  = (const float*)d_in[12];
    const float* fc2_b  = (const float*)d_in[13];
    float* out = (float*)d_out;

    bf16 *xw, *qkvbuf, *attn, *yn, *m1;
    bf16 *wt_qkv, *wt_proj, *wt_fc1, *wt_fc2;
    cudaGetSymbolAddress((void**)&xw,      g_xw);
    cudaGetSymbolAddress((void**)&qkvbuf,  g_qkv);
    cudaGetSymbolAddress((void**)&attn,    g_attn);
    cudaGetSymbolAddress((void**)&yn,      g_yn);
    cudaGetSymbolAddress((void**)&m1,      g_m1);
    cudaGetSymbolAddress((void**)&wt_qkv,  g_wt_qkv);
    cudaGetSymbolAddress((void**)&wt_proj, g_wt_proj);
    cudaGetSymbolAddress((void**)&wt_fc1,  g_wt_fc1);
    cudaGetSymbolAddress((void**)&wt_fc2,  g_wt_fc2);

    const int SMEM = 8 * ASTG;   // 81920 B
    cudaFuncSetAttribute((mma_gemm<0, bf16>),  cudaFuncAttributeMaxDynamicSharedMemorySize, SMEM);
    cudaFuncSetAttribute((mma_gemm<1, bf16>),  cudaFuncAttributeMaxDynamicSharedMemorySize, SMEM);
    cudaFuncSetAttribute((mma_gemm<3, float>), cudaFuncAttributeMaxDynamicSharedMemorySize, SMEM);
    const int PSMEM = 3 * PSTG;  // 92160 B
    cudaFuncSetAttribute(proj_ln_kernel, cudaFuncAttributeMaxDynamicSharedMemorySize, PSMEM);

    dim3 t32(32, 8);
    transpose_kernel<<<dim3(768/32, 256/32),  t32>>>(qkv_w,  wt_qkv,  256, 768);
    transpose_kernel<<<dim3(256/32, 256/32),  t32>>>(proj_w, wt_proj, 256, 256);
    transpose_kernel<<<dim3(1024/32, 256/32), t32>>>(fc1_w,  wt_fc1,  256, 1024);
    transpose_kernel<<<dim3(256/32, 1024/32), t32>>>(fc2_w,  wt_fc2,  1024, 256);

    // 1) LN1 + cyclic shift + window partition (bf16 out)
    ln_kernel<<<ROWS/8, 256>>>(x, n1g, n1b, xw, 1);
    // 2) QKV GEMM: [65536,256] @ [256,768] -> bf16
    mma_gemm<0, bf16><<<dim3(768/128, ROWS/128), 256, SMEM>>>(xw, wt_qkv, qkv_b, nullptr,
                                                              qkvbuf, ROWS, 768, 256);
    // 3) windowed attention (tensor cores) -> bf16
    attn_kernel<<<ROWS/64*HEADS, 128>>>(qkvbuf, rpb, attn);
    // 4) proj GEMM + scatter + residual(x) + LN2 fused -> yn (bf16)
    proj_ln_kernel<<<ROWS/128, 256, PSMEM>>>(attn, wt_proj, proj_b, x, n2g, n2b, yn);
    // 5) fc1 + exact GELU -> bf16
    mma_gemm<1, bf16><<<dim3(1024/128, ROWS/128), 256, SMEM>>>(yn, wt_fc1, fc1_b, nullptr,
                                                               m1, ROWS, 1024, 256);
    // 6) fc2 + residual with ORIGINAL shortcut x -> out (fp32)
    mma_gemm<3, float><<<dim3(256/128, ROWS/128), 256, SMEM>>>(m1, wt_fc2, fc2_b, x,
                                                               out, ROWS, 256, 1024);
}